// round 11
// baseline (speedup 1.0000x reference)
#include <cuda_runtime.h>
#include <cuda_fp16.h>
#include <math.h>
#include <stdint.h>

#define EDIM 1024
#define TLEN 1024
#define BATCH 4
#define NHEAD 16
#define HDIM 64
#define MROWS (BATCH * TLEN)   // 4096

// ---------------- scratch (device globals: no runtime allocation) ----------
__device__ __align__(128) __half g_hx[3][(size_t)MROWS * EDIM]; // q,k,v inputs fp16
__device__ __align__(128) __half g_hw[4][(size_t)EDIM * EDIM];  // Wq,Wk,Wv,Wo fp16
__device__ __align__(128) __half g_qh[(size_t)MROWS * EDIM];    // Q proj (x0.125)
__device__ __align__(128) __half g_kh[(size_t)MROWS * EDIM];
__device__ __align__(128) __half g_vh[(size_t)MROWS * EDIM];
__device__ __align__(128) __half g_atth[(size_t)MROWS * EDIM];
__device__ __align__(128) float  g_o[(size_t)MROWS * EDIM];

// ============================ helpers =======================================
__device__ __forceinline__ uint32_t smem_u32(const void* p) {
    uint32_t a;
    asm("{ .reg .u64 t; cvta.to.shared.u64 t, %1; cvt.u32.u64 %0, t; }"
        : "=r"(a) : "l"(p));
    return a;
}
__device__ __forceinline__ void cp_async16(uint32_t dst, const void* src) {
    asm volatile("cp.async.cg.shared.global [%0], [%1], 16;"
                 :: "r"(dst), "l"(src));
}
#define CP_COMMIT() asm volatile("cp.async.commit_group;" ::: "memory")
#define CP_WAIT0()  asm volatile("cp.async.wait_group 0;" ::: "memory")
#define CP_WAIT1()  asm volatile("cp.async.wait_group 1;" ::: "memory")

__device__ __forceinline__ void mma_f16(float* d, const uint32_t* a,
                                        const uint32_t* b) {
    asm volatile(
        "mma.sync.aligned.m16n8k16.row.col.f32.f16.f16.f32 "
        "{%0,%1,%2,%3}, {%4,%5,%6,%7}, {%8,%9}, {%0,%1,%2,%3};"
        : "+f"(d[0]), "+f"(d[1]), "+f"(d[2]), "+f"(d[3])
        : "r"(a[0]), "r"(a[1]), "r"(a[2]), "r"(a[3]),
          "r"(b[0]), "r"(b[1]));
}
__device__ __forceinline__ void ldsm_x4(uint32_t* r, uint32_t addr) {
    asm volatile("ldmatrix.sync.aligned.m8n8.x4.shared.b16 {%0,%1,%2,%3}, [%4];"
                 : "=r"(r[0]), "=r"(r[1]), "=r"(r[2]), "=r"(r[3]) : "r"(addr));
}
__device__ __forceinline__ void ldsm_x2(uint32_t* r, uint32_t addr) {
    asm volatile("ldmatrix.sync.aligned.m8n8.x2.shared.b16 {%0,%1}, [%2];"
                 : "=r"(r[0]), "=r"(r[1]) : "r"(addr));
}
__device__ __forceinline__ void ldsm_x2_t(uint32_t* r, uint32_t addr) {
    asm volatile("ldmatrix.sync.aligned.m8n8.x2.trans.shared.b16 {%0,%1}, [%2];"
                 : "=r"(r[0]), "=r"(r[1]) : "r"(addr));
}

// ============================================================================
// Batched fp32 -> fp16 convert, MLP=4. Activations: exactly 4 grid-strides;
// weights: exactly 1 (sizes divide the fixed grid).
// ============================================================================
#define CVT_GRID_X 1024
struct CvtArgs { const float* x[7]; __half* y[7]; };

__global__ __launch_bounds__(256) void cvt7_kernel(CvtArgs args)
{
    const int z = blockIdx.y;
    const float* __restrict__ x = args.x[z];
    __half* __restrict__ y = args.y[z];
    const int i = blockIdx.x * 256 + threadIdx.x;
    const int stride = CVT_GRID_X * 256;   // 262144

    if (z < 3) {
        // n4 = 1048576 = 4 * stride : issue all 4 loads, then store
        float4 v0 = *(const float4*)&x[(size_t)(i + 0 * stride) * 4];
        float4 v1 = *(const float4*)&x[(size_t)(i + 1 * stride) * 4];
        float4 v2 = *(const float4*)&x[(size_t)(i + 2 * stride) * 4];
        float4 v3 = *(const float4*)&x[(size_t)(i + 3 * stride) * 4];
#define CVT_ST(v, ii) do {                                        \
        __half2 h0 = __floats2half2_rn((v).x, (v).y);             \
        __half2 h1 = __floats2half2_rn((v).z, (v).w);             \
        uint2 oo = make_uint2(*(uint32_t*)&h0, *(uint32_t*)&h1);  \
        *(uint2*)&y[(size_t)(ii) * 4] = oo; } while (0)
        CVT_ST(v0, i + 0 * stride);
        CVT_ST(v1, i + 1 * stride);
        CVT_ST(v2, i + 2 * stride);
        CVT_ST(v3, i + 3 * stride);
    } else {
        // n4 = 262144 = stride
        float4 v0 = *(const float4*)&x[(size_t)i * 4];
        CVT_ST(v0, i);
#undef CVT_ST
    }
}

// ============================================================================
// fp16 GEMM core (shared by single + batched-QKV kernels).
// 128x128 tile, BK=64, 3-stage cp.async, 8 warps 2Mx4N, ldmatrix fragments.
// ============================================================================
#define HSTR 72
#define HTILEB (128 * HSTR * 2)       // 18432 B
#define GEMMH_SMEM (3 * 2 * HTILEB)   // 110592 B

__device__ __forceinline__ void gemm_h_body(
    const __half* __restrict__ A, const __half* __restrict__ W,
    const float* __restrict__ bias, float* __restrict__ Cf,
    __half* __restrict__ Ch, float oscale, char* smraw)
{
    const uint32_t sm0 = smem_u32(smraw);

    const int t    = threadIdx.x;
    const int wid  = t >> 5;
    const int lane = t & 31;
    const int grp  = lane >> 2;
    const int tig  = lane & 3;
    const int wm   = (wid >> 2) * 64;
    const int wn   = (wid & 3) * 32;
    const int m0   = blockIdx.y * 128;
    const int n0   = blockIdx.x * 128;

    const int lr = t >> 1;
    const int cc = (t & 1) * 4;

    const int laRow = lane & 15, laCol = (lane >> 4) * 8;
    const int lbRow = lane & 7,  lbCol = ((lane >> 3) & 1) * 8;

    float acc[4][4][4];
#pragma unroll
    for (int mi = 0; mi < 4; mi++)
#pragma unroll
        for (int nj = 0; nj < 4; nj++)
#pragma unroll
            for (int q = 0; q < 4; q++) acc[mi][nj][q] = 0.0f;

#pragma unroll
    for (int s = 0; s < 2; s++) {
        uint32_t dA = sm0 + s * 2 * HTILEB;
        uint32_t dB = dA + HTILEB;
        const int k0 = s * 64;
#pragma unroll
        for (int j = 0; j < 4; j++) {
            int c = cc + j;
            cp_async16(dA + (lr * HSTR + c * 8) * 2,
                       A + (size_t)(m0 + lr) * EDIM + k0 + c * 8);
            cp_async16(dB + (lr * HSTR + c * 8) * 2,
                       W + (size_t)(n0 + lr) * EDIM + k0 + c * 8);
        }
        CP_COMMIT();
    }

    const int NIT = EDIM / 64;   // 16
    int stage = 0;
    for (int it = 0; it < NIT; it++) {
        if (it + 1 < NIT) { CP_WAIT1(); } else { CP_WAIT0(); }
        __syncthreads();

        if (it + 2 < NIT) {
            int ps = stage + 2; if (ps >= 3) ps -= 3;
            const int k0 = (it + 2) * 64;
            uint32_t dA = sm0 + ps * 2 * HTILEB;
            uint32_t dB = dA + HTILEB;
#pragma unroll
            for (int j = 0; j < 4; j++) {
                int c = cc + j;
                cp_async16(dA + (lr * HSTR + c * 8) * 2,
                           A + (size_t)(m0 + lr) * EDIM + k0 + c * 8);
                cp_async16(dB + (lr * HSTR + c * 8) * 2,
                           W + (size_t)(n0 + lr) * EDIM + k0 + c * 8);
            }
            CP_COMMIT();
        }

        const uint32_t aS = sm0 + stage * 2 * HTILEB;
        const uint32_t bS = aS + HTILEB;

#pragma unroll
        for (int ks = 0; ks < 4; ks++) {
            uint32_t af[4][4], bf[4][2];
#pragma unroll
            for (int mi = 0; mi < 4; mi++)
                ldsm_x4(af[mi], aS + ((wm + mi * 16 + laRow) * HSTR
                                      + ks * 16 + laCol) * 2);
#pragma unroll
            for (int nj = 0; nj < 4; nj++)
                ldsm_x2(bf[nj], bS + ((wn + nj * 8 + lbRow) * HSTR
                                      + ks * 16 + lbCol) * 2);
#pragma unroll
            for (int mi = 0; mi < 4; mi++)
#pragma unroll
                for (int nj = 0; nj < 4; nj++)
                    mma_f16(acc[mi][nj], af[mi], bf[nj]);
        }

        if (++stage >= 3) stage = 0;
    }

#pragma unroll
    for (int mi = 0; mi < 4; mi++) {
        int rg = m0 + wm + mi * 16 + grp;
#pragma unroll
        for (int nj = 0; nj < 4; nj++) {
            int cg = n0 + wn + nj * 8 + tig * 2;
            float2 bv = *(const float2*)&bias[cg];
            float o00 = (acc[mi][nj][0] + bv.x) * oscale;
            float o01 = (acc[mi][nj][1] + bv.y) * oscale;
            float o10 = (acc[mi][nj][2] + bv.x) * oscale;
            float o11 = (acc[mi][nj][3] + bv.y) * oscale;
            if (Ch) {
                *(__half2*)&Ch[(size_t)rg * EDIM + cg]       = __floats2half2_rn(o00, o01);
                *(__half2*)&Ch[(size_t)(rg + 8) * EDIM + cg] = __floats2half2_rn(o10, o11);
            } else {
                *(float2*)&Cf[(size_t)rg * EDIM + cg]       = make_float2(o00, o01);
                *(float2*)&Cf[(size_t)(rg + 8) * EDIM + cg] = make_float2(o10, o11);
            }
        }
    }
}

// batched QKV: blockIdx.z selects the problem
struct G3Args {
    const __half* A[3]; const __half* W[3];
    const float* bias[3]; __half* C[3]; float oscale[3];
};

__global__ __launch_bounds__(256, 2) void gemm_h3(G3Args args)
{
    extern __shared__ char smraw[];
    const int z = blockIdx.z;
    gemm_h_body(args.A[z], args.W[z], args.bias[z], nullptr,
                args.C[z], args.oscale[z], smraw);
}

__global__ __launch_bounds__(256, 2) void gemm_h(
    const __half* __restrict__ A, const __half* __restrict__ W,
    const float* __restrict__ bias, float* __restrict__ Cf,
    __half* __restrict__ Ch, float oscale)
{
    extern __shared__ char smraw[];
    gemm_h_body(A, W, bias, Cf, Ch, oscale, smraw);
}

// ============================================================================
// fp16 flash attention: 128 q x (b*h) per block, 512 threads (16 warps 8Mx2N).
// Same per-warp program as the proven 64-q version; half the block-tiles.
// smem bytes: Qs 128x72h @0, Ks 2x64x72h @18432, Vs @36864, Ps 128x72h @55296,
//             red float[256] @73728.  total 74752.
// ============================================================================
#define ATTNH_SMEM (73728 + 1024)

__global__ __launch_bounds__(512, 1) void attn_h(const int* __restrict__ mask)
{
    extern __shared__ char smraw[];
    __half* Ps  = (__half*)(smraw + 55296);
    float*  red = (float*)(smraw + 73728);

    const uint32_t sQ = smem_u32(smraw);
    const uint32_t sK = sQ + 18432;
    const uint32_t sV = sQ + 36864;
    const uint32_t sP = sQ + 55296;

    const int t    = threadIdx.x;
    const int wid  = t >> 5;           // 0..15
    const int lane = t & 31;
    const int grp  = lane >> 2;
    const int tig  = lane & 3;
    const int wm   = (wid & 7) * 16;   // 8 M-groups
    const int wn   = (wid >> 3) * 32;  // 2 N-groups
    const int wnx  = wid >> 3;
    const int q0   = blockIdx.x * 128;
    const int bh   = blockIdx.y;
    const int b    = bh >> 4;
    const int h    = bh & 15;
    const int hofs = h * HDIM;

    const int qrow = t >> 2;           // 0..127
    const int qcc  = (t & 3) * 2;
    const int kvrow = t >> 3;          // 0..63
    const int kvc   = t & 7;

    const int laRow = lane & 15, laCol = (lane >> 4) * 8;
    const int lbRow = lane & 7,  lbCol = ((lane >> 3) & 1) * 8;

    // Q (128 rows) + first K/V tile (64 rows)
#pragma unroll
    for (int j = 0; j < 2; j++) {
        int c = qcc + j;
        size_t gq = (size_t)(b * TLEN + q0 + qrow) * EDIM + hofs + c * 8;
        cp_async16(sQ + (qrow * HSTR + c * 8) * 2, g_qh + gq);
    }
    {
        size_t gkv = (size_t)(b * TLEN + kvrow) * EDIM + hofs + kvc * 8;
        cp_async16(sK + (kvrow * HSTR + kvc * 8) * 2, g_kh + gkv);
        cp_async16(sV + (kvrow * HSTR + kvc * 8) * 2, g_vh + gkv);
    }
    CP_COMMIT();

    const int r0 = wm + grp;
    const int r1 = wm + grp + 8;

    float o[4][4];
#pragma unroll
    for (int nf = 0; nf < 4; nf++)
#pragma unroll
        for (int q = 0; q < 4; q++) o[nf][q] = 0.0f;
    float mo0 = -1e30f, mo1 = -1e30f, L0 = 0.0f, L1 = 0.0f;

    for (int kt = 0; kt < TLEN / 64; kt++) {
        const int cur = kt & 1;
        CP_WAIT0();
        __syncthreads();

        if (kt + 1 < TLEN / 64) {
            const int nb = cur ^ 1;
            size_t gkv = (size_t)(b * TLEN + (kt + 1) * 64 + kvrow) * EDIM + hofs + kvc * 8;
            cp_async16(sK + nb * 9216 + (kvrow * HSTR + kvc * 8) * 2, g_kh + gkv);
            cp_async16(sV + nb * 9216 + (kvrow * HSTR + kvc * 8) * 2, g_vh + gkv);
            CP_COMMIT();
        }

        // hoisted mask loads
        int2 mreg0[4], mreg1[4];
        const size_t mbase = (size_t)(b * TLEN + q0 + r0) * TLEN + kt * 64 + wn + tig * 2;
#pragma unroll
        for (int nf = 0; nf < 4; nf++) {
            mreg0[nf] = *(const int2*)&mask[mbase + nf * 8];
            mreg1[nf] = *(const int2*)&mask[mbase + (size_t)8 * TLEN + nf * 8];
        }

        const uint32_t kB = sK + cur * 9216;
        const uint32_t vB = sV + cur * 9216;

        // ---- S = Q @ K^T ----
        float s[4][4];
#pragma unroll
        for (int nf = 0; nf < 4; nf++)
#pragma unroll
            for (int q = 0; q < 4; q++) s[nf][q] = 0.0f;

#pragma unroll
        for (int ks = 0; ks < 4; ks++) {
            uint32_t af[4];
            ldsm_x4(af, sQ + ((wm + laRow) * HSTR + ks * 16 + laCol) * 2);
#pragma unroll
            for (int nf = 0; nf < 4; nf++) {
                uint32_t bf[2];
                ldsm_x2(bf, kB + ((wn + nf * 8 + lbRow) * HSTR + ks * 16 + lbCol) * 2);
                mma_f16(s[nf], af, bf);
            }
        }

        // ---- mask + warp-half max ----
        float mx0 = -1e30f, mx1 = -1e30f;
#pragma unroll
        for (int nf = 0; nf < 4; nf++) {
            s[nf][0] = (mreg0[nf].x == 0) ? -1.0e9f : s[nf][0];
            s[nf][1] = (mreg0[nf].y == 0) ? -1.0e9f : s[nf][1];
            s[nf][2] = (mreg1[nf].x == 0) ? -1.0e9f : s[nf][2];
            s[nf][3] = (mreg1[nf].y == 0) ? -1.0e9f : s[nf][3];
            mx0 = fmaxf(mx0, fmaxf(s[nf][0], s[nf][1]));
            mx1 = fmaxf(mx1, fmaxf(s[nf][2], s[nf][3]));
        }
        mx0 = fmaxf(mx0, __shfl_xor_sync(0xffffffffu, mx0, 1));
        mx0 = fmaxf(mx0, __shfl_xor_sync(0xffffffffu, mx0, 2));
        mx1 = fmaxf(mx1, __shfl_xor_sync(0xffffffffu, mx1, 1));
        mx1 = fmaxf(mx1, __shfl_xor_sync(0xffffffffu, mx1, 2));
        if (tig == 0) {
            red[r0 * 2 + wnx] = mx0;
            red[r1 * 2 + wnx] = mx1;
        }
        __syncthreads();

        float rm0 = fmaxf(red[r0 * 2], red[r0 * 2 + 1]);
        float rm1 = fmaxf(red[r1 * 2], red[r1 * 2 + 1]);
        float mN0 = fmaxf(mo0, rm0);
        float mN1 = fmaxf(mo1, rm1);
        float a0  = __expf(mo0 - mN0);
        float a1  = __expf(mo1 - mN1);
        mo0 = mN0; mo1 = mN1;

        float sum0 = 0.0f, sum1 = 0.0f;
#pragma unroll
        for (int nf = 0; nf < 4; nf++) {
            float p00 = __expf(s[nf][0] - mN0);
            float p01 = __expf(s[nf][1] - mN0);
            float p10 = __expf(s[nf][2] - mN1);
            float p11 = __expf(s[nf][3] - mN1);
            sum0 += p00 + p01;
            sum1 += p10 + p11;
            int col = wn + nf * 8 + tig * 2;
            *(__half2*)&Ps[r0 * HSTR + col] = __floats2half2_rn(p00, p01);
            *(__half2*)&Ps[r1 * HSTR + col] = __floats2half2_rn(p10, p11);
            o[nf][0] *= a0; o[nf][1] *= a0;
            o[nf][2] *= a1; o[nf][3] *= a1;
        }
        sum0 += __shfl_xor_sync(0xffffffffu, sum0, 1);
        sum0 += __shfl_xor_sync(0xffffffffu, sum0, 2);
        sum1 += __shfl_xor_sync(0xffffffffu, sum1, 1);
        sum1 += __shfl_xor_sync(0xffffffffu, sum1, 2);
        L0 = L0 * a0 + sum0;
        L1 = L1 * a1 + sum1;
        __syncthreads();   // Ps visible block-wide

        // ---- O += P @ V (V [k][d] via ldmatrix.trans) ----
#pragma unroll
        for (int ks = 0; ks < 4; ks++) {
            uint32_t af[4];
            ldsm_x4(af, sP + ((wm + laRow) * HSTR + ks * 16 + laCol) * 2);
#pragma unroll
            for (int nf = 0; nf < 4; nf++) {
                uint32_t bf[2];
                ldsm_x2_t(bf, vB + ((ks * 16 + laRow) * HSTR + wn + nf * 8) * 2);
                mma_f16(o[nf], af, bf);
            }
        }
    }

    if (tig == 0) {
        red[r0 * 2 + wnx] = L0;
        red[r1 * 2 + wnx] = L1;
    }
    __syncthreads();
    const float linv0 = 1.0f / (red[r0 * 2] + red[r0 * 2 + 1]);
    const float linv1 = 1.0f / (red[r1 * 2] + red[r1 * 2 + 1]);

    const size_t orow0 = (size_t)(b * TLEN + q0 + r0) * EDIM + hofs;
    const size_t orow1 = (size_t)(b * TLEN + q0 + r1) * EDIM + hofs;
#pragma unroll
    for (int nf = 0; nf < 4; nf++) {
        int col = wn + nf * 8 + tig * 2;
        *(__half2*)&g_atth[orow0 + col] =
            __floats2half2_rn(o[nf][0] * linv0, o[nf][1] * linv0);
        *(__half2*)&g_atth[orow1 + col] =
            __floats2half2_rn(o[nf][2] * linv1, o[nf][3] * linv1);
    }
}

// ============================================================================
// LayerNorm over E=1024, one block (256 threads) per row.
// ============================================================================
__global__ __launch_bounds__(256) void ln_kernel(
    const float* __restrict__ X, const float* __restrict__ gam,
    const float* __restrict__ bet, float* __restrict__ out)
{
    const int row = blockIdx.x;
    const int t   = threadIdx.x;
    __shared__ float red[8];

    float4 x = *(const float4*)&X[row * EDIM + t * 4];
    float s = x.x + x.y + x.z + x.w;
#pragma unroll
    for (int ofs = 16; ofs; ofs >>= 1) s += __shfl_xor_sync(0xffffffffu, s, ofs);
    if ((t & 31) == 0) red[t >> 5] = s;
    __syncthreads();
    float tot = 0.0f;
#pragma unroll
    for (int i = 0; i < 8; i++) tot += red[i];
    float mu = tot * (1.0f / 1024.0f);

    float d0 = x.x - mu, d1 = x.y - mu, d2 = x.z - mu, d3 = x.w - mu;
    float sq = d0 * d0 + d1 * d1 + d2 * d2 + d3 * d3;
    __syncthreads();
#pragma unroll
    for (int ofs = 16; ofs; ofs >>= 1) sq += __shfl_xor_sync(0xffffffffu, sq, ofs);
    if ((t & 31) == 0) red[t >> 5] = sq;
    __syncthreads();
    float vtot = 0.0f;
#pragma unroll
    for (int i = 0; i < 8; i++) vtot += red[i];
    float inv = rsqrtf(vtot * (1.0f / 1024.0f) + 1e-5f);

    float4 g  = *(const float4*)&gam[t * 4];
    float4 be = *(const float4*)&bet[t * 4];
    float4 o4;
    o4.x = d0 * inv * g.x + be.x;
    o4.y = d1 * inv * g.y + be.y;
    o4.z = d2 * inv * g.z + be.z;
    o4.w = d3 * inv * g.w + be.w;
    *(float4*)&out[row * EDIM + t * 4] = o4;
}

// ============================================================================
extern "C" void kernel_launch(void* const* d_in, const int* in_sizes, int n_in,
                              void* d_out, int out_size)
{
    const float* query = (const float*)d_in[0];
    const float* key   = (const float*)d_in[1];
    const float* value = (const float*)d_in[2];
    const int*   mask  = (const int*)d_in[3];
    const float* Wq    = (const float*)d_in[4];
    const float* bq    = (const float*)d_in[5];
    const float* Wk    = (const float*)d_in[6];
    const float* bk    = (const float*)d_in[7];
    const float* Wv    = (const float*)d_in[8];
    const float* bv    = (const float*)d_in[9];
    const float* Wo    = (const float*)d_in[10];
    const float* bo    = (const float*)d_in[11];
    const float* gamma = (const float*)d_in[12];
    const float* beta  = (const float*)d_in[13];
    float* out = (float*)d_out;

    __half *hx, *hw, *qh, *kh, *vh, *atth;
    float* go;
    cudaGetSymbolAddress((void**)&hx,   g_hx);
    cudaGetSymbolAddress((void**)&hw,   g_hw);
    cudaGetSymbolAddress((void**)&qh,   g_qh);
    cudaGetSymbolAddress((void**)&kh,   g_kh);
    cudaGetSymbolAddress((void**)&vh,   g_vh);
    cudaGetSymbolAddress((void**)&atth, g_atth);
    cudaGetSymbolAddress((void**)&go,   g_o);

    const size_t ACT = (size_t)MROWS * EDIM;
    const size_t WSZ = (size_t)EDIM * EDIM;

    cudaFuncSetAttribute(gemm_h,
                         cudaFuncAttributeMaxDynamicSharedMemorySize, GEMMH_SMEM);
    cudaFuncSetAttribute(gemm_h3,
                         cudaFuncAttributeMaxDynamicSharedMemorySize, GEMMH_SMEM);
    cudaFuncSetAttribute(attn_h,
                         cudaFuncAttributeMaxDynamicSharedMemorySize, ATTNH_SMEM);

    // fp32 -> fp16 conversion (MLP=4)
    CvtArgs ca;
    ca.x[0] = query; ca.x[1] = key; ca.x[2] = value;
    ca.x[3] = Wq; ca.x[4] = Wk; ca.x[5] = Wv; ca.x[6] = Wo;
    ca.y[0] = hx;           ca.y[1] = hx + ACT;   ca.y[2] = hx + 2 * ACT;
    ca.y[3] = hw;           ca.y[4] = hw + WSZ;
    ca.y[5] = hw + 2 * WSZ; ca.y[6] = hw + 3 * WSZ;
    dim3 gc(CVT_GRID_X, 7);
    cvt7_kernel<<<gc, 256>>>(ca);

    // batched QKV projections
    G3Args g3;
    g3.A[0] = hx;           g3.A[1] = hx + ACT;   g3.A[2] = hx + 2 * ACT;
    g3.W[0] = hw;           g3.W[1] = hw + WSZ;   g3.W[2] = hw + 2 * WSZ;
    g3.bias[0] = bq; g3.bias[1] = bk; g3.bias[2] = bv;
    g3.C[0] = qh; g3.C[1] = kh; g3.C[2] = vh;
    g3.oscale[0] = 0.125f; g3.oscale[1] = 1.0f; g3.oscale[2] = 1.0f;
    dim3 gg3(EDIM / 128, MROWS / 128, 3);   // (8, 32, 3)
    gemm_h3<<<gg3, 256, GEMMH_SMEM>>>(g3);

    dim3 ga(TLEN / 128, BATCH * NHEAD);     // (8, 64)
    attn_h<<<ga, 512, ATTNH_SMEM>>>(mask);

    dim3 gg(EDIM / 128, MROWS / 128);       // (8, 32)
    gemm_h<<<gg, 256, GEMMH_SMEM>>>(atth, hw + 3 * WSZ, bo, go, nullptr, 1.0f);

    ln_kernel<<<MROWS, 256>>>(go, gamma, beta, out);
}

// round 12
// speedup vs baseline: 1.0830x; 1.0830x over previous
#include <cuda_runtime.h>
#include <cuda_fp16.h>
#include <math.h>
#include <stdint.h>

#define EDIM 1024
#define TLEN 1024
#define BATCH 4
#define NHEAD 16
#define HDIM 64
#define MROWS (BATCH * TLEN)   // 4096

// ---------------- scratch (device globals: no runtime allocation) ----------
__device__ __align__(128) __half g_hx[3][(size_t)MROWS * EDIM]; // q,k,v inputs fp16
__device__ __align__(128) __half g_hw[4][(size_t)EDIM * EDIM];  // Wq,Wk,Wv,Wo fp16
__device__ __align__(128) __half g_qh[(size_t)MROWS * EDIM];    // Q proj (x0.125)
__device__ __align__(128) __half g_kh[(size_t)MROWS * EDIM];
__device__ __align__(128) __half g_vh[(size_t)MROWS * EDIM];
__device__ __align__(128) __half g_atth[(size_t)MROWS * EDIM];
__device__ __align__(128) float  g_o[(size_t)MROWS * EDIM];

// ============================ helpers =======================================
__device__ __forceinline__ uint32_t smem_u32(const void* p) {
    uint32_t a;
    asm("{ .reg .u64 t; cvta.to.shared.u64 t, %1; cvt.u32.u64 %0, t; }"
        : "=r"(a) : "l"(p));
    return a;
}
__device__ __forceinline__ void cp_async16(uint32_t dst, const void* src) {
    asm volatile("cp.async.cg.shared.global [%0], [%1], 16;"
                 :: "r"(dst), "l"(src));
}
#define CP_COMMIT() asm volatile("cp.async.commit_group;" ::: "memory")
#define CP_WAIT0()  asm volatile("cp.async.wait_group 0;" ::: "memory")
#define CP_WAIT1()  asm volatile("cp.async.wait_group 1;" ::: "memory")

__device__ __forceinline__ void mma_f16(float* d, const uint32_t* a,
                                        const uint32_t* b) {
    asm volatile(
        "mma.sync.aligned.m16n8k16.row.col.f32.f16.f16.f32 "
        "{%0,%1,%2,%3}, {%4,%5,%6,%7}, {%8,%9}, {%0,%1,%2,%3};"
        : "+f"(d[0]), "+f"(d[1]), "+f"(d[2]), "+f"(d[3])
        : "r"(a[0]), "r"(a[1]), "r"(a[2]), "r"(a[3]),
          "r"(b[0]), "r"(b[1]));
}
__device__ __forceinline__ void ldsm_x4(uint32_t* r, uint32_t addr) {
    asm volatile("ldmatrix.sync.aligned.m8n8.x4.shared.b16 {%0,%1,%2,%3}, [%4];"
                 : "=r"(r[0]), "=r"(r[1]), "=r"(r[2]), "=r"(r[3]) : "r"(addr));
}
__device__ __forceinline__ void ldsm_x2(uint32_t* r, uint32_t addr) {
    asm volatile("ldmatrix.sync.aligned.m8n8.x2.shared.b16 {%0,%1}, [%2];"
                 : "=r"(r[0]), "=r"(r[1]) : "r"(addr));
}
__device__ __forceinline__ void ldsm_x2_t(uint32_t* r, uint32_t addr) {
    asm volatile("ldmatrix.sync.aligned.m8n8.x2.trans.shared.b16 {%0,%1}, [%2];"
                 : "=r"(r[0]), "=r"(r[1]) : "r"(addr));
}

// ============================================================================
// Batched fp32 -> fp16 convert, MLP=4.
// ============================================================================
#define CVT_GRID_X 1024
struct CvtArgs { const float* x[7]; __half* y[7]; };

__global__ __launch_bounds__(256) void cvt7_kernel(CvtArgs args)
{
    const int z = blockIdx.y;
    const float* __restrict__ x = args.x[z];
    __half* __restrict__ y = args.y[z];
    const int i = blockIdx.x * 256 + threadIdx.x;
    const int stride = CVT_GRID_X * 256;   // 262144

    if (z < 3) {
        float4 v0 = *(const float4*)&x[(size_t)(i + 0 * stride) * 4];
        float4 v1 = *(const float4*)&x[(size_t)(i + 1 * stride) * 4];
        float4 v2 = *(const float4*)&x[(size_t)(i + 2 * stride) * 4];
        float4 v3 = *(const float4*)&x[(size_t)(i + 3 * stride) * 4];
#define CVT_ST(v, ii) do {                                        \
        __half2 h0 = __floats2half2_rn((v).x, (v).y);             \
        __half2 h1 = __floats2half2_rn((v).z, (v).w);             \
        uint2 oo = make_uint2(*(uint32_t*)&h0, *(uint32_t*)&h1);  \
        *(uint2*)&y[(size_t)(ii) * 4] = oo; } while (0)
        CVT_ST(v0, i + 0 * stride);
        CVT_ST(v1, i + 1 * stride);
        CVT_ST(v2, i + 2 * stride);
        CVT_ST(v3, i + 3 * stride);
    } else {
        float4 v0 = *(const float4*)&x[(size_t)i * 4];
        CVT_ST(v0, i);
#undef CVT_ST
    }
}

// ============================================================================
// fp16 GEMM core. 128x128 tile, BK=64, 3-stage cp.async, 8 warps 2Mx4N.
// B fragments loaded pairwise with ldmatrix.x4 (24 LDSM/iter/warp).
// ============================================================================
#define HSTR 72
#define HTILEB (128 * HSTR * 2)       // 18432 B
#define GEMMH_SMEM (3 * 2 * HTILEB)   // 110592 B

__device__ __forceinline__ void gemm_h_body(
    const __half* __restrict__ A, const __half* __restrict__ W,
    const float* __restrict__ bias, float* __restrict__ Cf,
    __half* __restrict__ Ch, float oscale, char* smraw)
{
    const uint32_t sm0 = smem_u32(smraw);

    const int t    = threadIdx.x;
    const int wid  = t >> 5;
    const int lane = t & 31;
    const int grp  = lane >> 2;
    const int tig  = lane & 3;
    const int wm   = (wid >> 2) * 64;
    const int wn   = (wid & 3) * 32;
    const int m0   = blockIdx.y * 128;
    const int n0   = blockIdx.x * 128;

    const int lr = t >> 1;
    const int cc = (t & 1) * 4;

    const int laRow = lane & 15, laCol = (lane >> 4) * 8;
    // x4 pairwise B-frag addressing
    const int pbRow = ((lane >> 4) & 1) * 8 + (lane & 7);
    const int pbCol = ((lane >> 3) & 1) * 8;

    float acc[4][4][4];
#pragma unroll
    for (int mi = 0; mi < 4; mi++)
#pragma unroll
        for (int nj = 0; nj < 4; nj++)
#pragma unroll
            for (int q = 0; q < 4; q++) acc[mi][nj][q] = 0.0f;

#pragma unroll
    for (int s = 0; s < 2; s++) {
        uint32_t dA = sm0 + s * 2 * HTILEB;
        uint32_t dB = dA + HTILEB;
        const int k0 = s * 64;
#pragma unroll
        for (int j = 0; j < 4; j++) {
            int c = cc + j;
            cp_async16(dA + (lr * HSTR + c * 8) * 2,
                       A + (size_t)(m0 + lr) * EDIM + k0 + c * 8);
            cp_async16(dB + (lr * HSTR + c * 8) * 2,
                       W + (size_t)(n0 + lr) * EDIM + k0 + c * 8);
        }
        CP_COMMIT();
    }

    const int NIT = EDIM / 64;   // 16
    int stage = 0;
    for (int it = 0; it < NIT; it++) {
        if (it + 1 < NIT) { CP_WAIT1(); } else { CP_WAIT0(); }
        __syncthreads();

        if (it + 2 < NIT) {
            int ps = stage + 2; if (ps >= 3) ps -= 3;
            const int k0 = (it + 2) * 64;
            uint32_t dA = sm0 + ps * 2 * HTILEB;
            uint32_t dB = dA + HTILEB;
#pragma unroll
            for (int j = 0; j < 4; j++) {
                int c = cc + j;
                cp_async16(dA + (lr * HSTR + c * 8) * 2,
                           A + (size_t)(m0 + lr) * EDIM + k0 + c * 8);
                cp_async16(dB + (lr * HSTR + c * 8) * 2,
                           W + (size_t)(n0 + lr) * EDIM + k0 + c * 8);
            }
            CP_COMMIT();
        }

        const uint32_t aS = sm0 + stage * 2 * HTILEB;
        const uint32_t bS = aS + HTILEB;

#pragma unroll
        for (int ks = 0; ks < 4; ks++) {
            uint32_t af[4][4], bf[4][2];
#pragma unroll
            for (int mi = 0; mi < 4; mi++)
                ldsm_x4(af[mi], aS + ((wm + mi * 16 + laRow) * HSTR
                                      + ks * 16 + laCol) * 2);
#pragma unroll
            for (int njp = 0; njp < 2; njp++) {
                uint32_t r4[4];
                ldsm_x4(r4, bS + ((wn + njp * 16 + pbRow) * HSTR
                                  + ks * 16 + pbCol) * 2);
                bf[2 * njp][0] = r4[0]; bf[2 * njp][1] = r4[1];
                bf[2 * njp + 1][0] = r4[2]; bf[2 * njp + 1][1] = r4[3];
            }
#pragma unroll
            for (int mi = 0; mi < 4; mi++)
#pragma unroll
                for (int nj = 0; nj < 4; nj++)
                    mma_f16(acc[mi][nj], af[mi], bf[nj]);
        }

        if (++stage >= 3) stage = 0;
    }

#pragma unroll
    for (int mi = 0; mi < 4; mi++) {
        int rg = m0 + wm + mi * 16 + grp;
#pragma unroll
        for (int nj = 0; nj < 4; nj++) {
            int cg = n0 + wn + nj * 8 + tig * 2;
            float2 bv = *(const float2*)&bias[cg];
            float o00 = (acc[mi][nj][0] + bv.x) * oscale;
            float o01 = (acc[mi][nj][1] + bv.y) * oscale;
            float o10 = (acc[mi][nj][2] + bv.x) * oscale;
            float o11 = (acc[mi][nj][3] + bv.y) * oscale;
            if (Ch) {
                *(__half2*)&Ch[(size_t)rg * EDIM + cg]       = __floats2half2_rn(o00, o01);
                *(__half2*)&Ch[(size_t)(rg + 8) * EDIM + cg] = __floats2half2_rn(o10, o11);
            } else {
                *(float2*)&Cf[(size_t)rg * EDIM + cg]       = make_float2(o00, o01);
                *(float2*)&Cf[(size_t)(rg + 8) * EDIM + cg] = make_float2(o10, o11);
            }
        }
    }
}

struct G3Args {
    const __half* A[3]; const __half* W[3];
    const float* bias[3]; __half* C[3]; float oscale[3];
};

__global__ __launch_bounds__(256, 2) void gemm_h3(G3Args args)
{
    extern __shared__ char smraw[];
    const int z = blockIdx.z;
    gemm_h_body(args.A[z], args.W[z], args.bias[z], nullptr,
                args.C[z], args.oscale[z], smraw);
}

__global__ __launch_bounds__(256, 2) void gemm_h(
    const __half* __restrict__ A, const __half* __restrict__ W,
    const float* __restrict__ bias, float* __restrict__ Cf,
    __half* __restrict__ Ch, float oscale)
{
    extern __shared__ char smraw[];
    gemm_h_body(A, W, bias, Cf, Ch, oscale, smraw);
}

// ============================================================================
// fp16 flash attention (PROVEN R9 version): 64 q x (b*h) per block, 256 thr
// (8 warps 4M x 2N). S,PV on m16n8k16 via ldmatrix (V .trans); fp32 stats;
// cp.async double-buffered K/V; deferred l; 3 syncs/tile.
// ============================================================================
#define ATTNH_SMEM (55296 + 512)

__global__ __launch_bounds__(256, 2) void attn_h(const int* __restrict__ mask)
{
    extern __shared__ char smraw[];
    __half* Ps  = (__half*)(smraw + 23040 * 2);
    float*  red = (float*)(smraw + 55296);

    const uint32_t sQ = smem_u32(smraw);
    const uint32_t sK = sQ + 4608 * 2;
    const uint32_t sV = sQ + 13824 * 2;
    const uint32_t sP = sQ + 23040 * 2;

    const int t    = threadIdx.x;
    const int wid  = t >> 5;
    const int lane = t & 31;
    const int grp  = lane >> 2;
    const int tig  = lane & 3;
    const int wm   = (wid & 3) * 16;
    const int wn   = (wid >> 2) * 32;
    const int wnx  = wid >> 2;
    const int q0   = blockIdx.x * 64;
    const int bh   = blockIdx.y;
    const int b    = bh >> 4;
    const int h    = bh & 15;
    const int hofs = h * HDIM;

    const int lrow = t >> 2;          // loader row 0..63
    const int lcc  = (t & 3) * 2;

    const int laRow = lane & 15, laCol = (lane >> 4) * 8;
    const int lbRow = lane & 7,  lbCol = ((lane >> 3) & 1) * 8;

#pragma unroll
    for (int j = 0; j < 2; j++) {
        int c = lcc + j;
        size_t gq = (size_t)(b * TLEN + q0 + lrow) * EDIM + hofs + c * 8;
        cp_async16(sQ + (lrow * HSTR + c * 8) * 2, g_qh + gq);
        size_t gkv = (size_t)(b * TLEN + lrow) * EDIM + hofs + c * 8;
        cp_async16(sK + (lrow * HSTR + c * 8) * 2, g_kh + gkv);
        cp_async16(sV + (lrow * HSTR + c * 8) * 2, g_vh + gkv);
    }
    CP_COMMIT();

    const int r0 = wm + grp;
    const int r1 = wm + grp + 8;

    float o[4][4];
#pragma unroll
    for (int nf = 0; nf < 4; nf++)
#pragma unroll
        for (int q = 0; q < 4; q++) o[nf][q] = 0.0f;
    float mo0 = -1e30f, mo1 = -1e30f, L0 = 0.0f, L1 = 0.0f;

    for (int kt = 0; kt < TLEN / 64; kt++) {
        const int cur = kt & 1;
        CP_WAIT0();
        __syncthreads();

        if (kt + 1 < TLEN / 64) {
            const int nb = cur ^ 1;
            uint32_t kd = sK + nb * (64 * HSTR) * 2;
            uint32_t vd = sV + nb * (64 * HSTR) * 2;
#pragma unroll
            for (int j = 0; j < 2; j++) {
                int c = lcc + j;
                size_t gkv = (size_t)(b * TLEN + (kt + 1) * 64 + lrow) * EDIM + hofs + c * 8;
                cp_async16(kd + (lrow * HSTR + c * 8) * 2, g_kh + gkv);
                cp_async16(vd + (lrow * HSTR + c * 8) * 2, g_vh + gkv);
            }
            CP_COMMIT();
        }

        // hoisted mask loads
        int2 mreg0[4], mreg1[4];
        const size_t mbase = (size_t)(b * TLEN + q0 + r0) * TLEN + kt * 64 + wn + tig * 2;
#pragma unroll
        for (int nf = 0; nf < 4; nf++) {
            mreg0[nf] = *(const int2*)&mask[mbase + nf * 8];
            mreg1[nf] = *(const int2*)&mask[mbase + (size_t)8 * TLEN + nf * 8];
        }

        const uint32_t kB = sK + cur * (64 * HSTR) * 2;
        const uint32_t vB = sV + cur * (64 * HSTR) * 2;

        // ---- S = Q @ K^T ----
        float s[4][4];
#pragma unroll
        for (int nf = 0; nf < 4; nf++)
#pragma unroll
            for (int q = 0; q < 4; q++) s[nf][q] = 0.0f;

#pragma unroll
        for (int ks = 0; ks < 4; ks++) {
            uint32_t af[4];
            ldsm_x4(af, sQ + ((wm + laRow) * HSTR + ks * 16 + laCol) * 2);
#pragma unroll
            for (int nf = 0; nf < 4; nf++) {
                uint32_t bf[2];
                ldsm_x2(bf, kB + ((wn + nf * 8 + lbRow) * HSTR + ks * 16 + lbCol) * 2);
                mma_f16(s[nf], af, bf);
            }
        }

        // ---- mask + warp-half max ----
        float mx0 = -1e30f, mx1 = -1e30f;
#pragma unroll
        for (int nf = 0; nf < 4; nf++) {
            s[nf][0] = (mreg0[nf].x == 0) ? -1.0e9f : s[nf][0];
            s[nf][1] = (mreg0[nf].y == 0) ? -1.0e9f : s[nf][1];
            s[nf][2] = (mreg1[nf].x == 0) ? -1.0e9f : s[nf][2];
            s[nf][3] = (mreg1[nf].y == 0) ? -1.0e9f : s[nf][3];
            mx0 = fmaxf(mx0, fmaxf(s[nf][0], s[nf][1]));
            mx1 = fmaxf(mx1, fmaxf(s[nf][2], s[nf][3]));
        }
        mx0 = fmaxf(mx0, __shfl_xor_sync(0xffffffffu, mx0, 1));
        mx0 = fmaxf(mx0, __shfl_xor_sync(0xffffffffu, mx0, 2));
        mx1 = fmaxf(mx1, __shfl_xor_sync(0xffffffffu, mx1, 1));
        mx1 = fmaxf(mx1, __shfl_xor_sync(0xffffffffu, mx1, 2));
        if (tig == 0) {
            red[r0 * 2 + wnx] = mx0;
            red[r1 * 2 + wnx] = mx1;
        }
        __syncthreads();

        float rm0 = fmaxf(red[r0 * 2], red[r0 * 2 + 1]);
        float rm1 = fmaxf(red[r1 * 2], red[r1 * 2 + 1]);
        float mN0 = fmaxf(mo0, rm0);
        float mN1 = fmaxf(mo1, rm1);
        float a0  = __expf(mo0 - mN0);
        float a1  = __expf(mo1 - mN1);
        mo0 = mN0; mo1 = mN1;

        float sum0 = 0.0f, sum1 = 0.0f;
#pragma unroll
        for (int nf = 0; nf < 4; nf++) {
            float p00 = __expf(s[nf][0] - mN0);
            float p01 = __expf(s[nf][1] - mN0);
            float p10 = __expf(s[nf][2] - mN1);
            float p11 = __expf(s[nf][3] - mN1);
            sum0 += p00 + p01;
            sum1 += p10 + p11;
            int col = wn + nf * 8 + tig * 2;
            *(__half2*)&Ps[r0 * HSTR + col] = __floats2half2_rn(p00, p01);
            *(__half2*)&Ps[r1 * HSTR + col] = __floats2half2_rn(p10, p11);
            o[nf][0] *= a0; o[nf][1] *= a0;
            o[nf][2] *= a1; o[nf][3] *= a1;
        }
        sum0 += __shfl_xor_sync(0xffffffffu, sum0, 1);
        sum0 += __shfl_xor_sync(0xffffffffu, sum0, 2);
        sum1 += __shfl_xor_sync(0xffffffffu, sum1, 1);
        sum1 += __shfl_xor_sync(0xffffffffu, sum1, 2);
        L0 = L0 * a0 + sum0;
        L1 = L1 * a1 + sum1;
        __syncthreads();   // Ps visible block-wide

        // ---- O += P @ V (V [k][d] via ldmatrix.trans) ----
#pragma unroll
        for (int ks = 0; ks < 4; ks++) {
            uint32_t af[4];
            ldsm_x4(af, sP + ((wm + laRow) * HSTR + ks * 16 + laCol) * 2);
#pragma unroll
            for (int nf = 0; nf < 4; nf++) {
                uint32_t bf[2];
                ldsm_x2_t(bf, vB + ((ks * 16 + laRow) * HSTR + wn + nf * 8) * 2);
                mma_f16(o[nf], af, bf);
            }
        }
    }

    if (tig == 0) {
        red[r0 * 2 + wnx] = L0;
        red[r1 * 2 + wnx] = L1;
    }
    __syncthreads();
    const float linv0 = 1.0f / (red[r0 * 2] + red[r0 * 2 + 1]);
    const float linv1 = 1.0f / (red[r1 * 2] + red[r1 * 2 + 1]);

    const size_t orow0 = (size_t)(b * TLEN + q0 + r0) * EDIM + hofs;
    const size_t orow1 = (size_t)(b * TLEN + q0 + r1) * EDIM + hofs;
#pragma unroll
    for (int nf = 0; nf < 4; nf++) {
        int col = wn + nf * 8 + tig * 2;
        *(__half2*)&g_atth[orow0 + col] =
            __floats2half2_rn(o[nf][0] * linv0, o[nf][1] * linv0);
        *(__half2*)&g_atth[orow1 + col] =
            __floats2half2_rn(o[nf][2] * linv1, o[nf][3] * linv1);
    }
}

// ============================================================================
// LayerNorm over E=1024, one block (256 threads) per row.
// ============================================================================
__global__ __launch_bounds__(256) void ln_kernel(
    const float* __restrict__ X, const float* __restrict__ gam,
    const float* __restrict__ bet, float* __restrict__ out)
{
    const int row = blockIdx.x;
    const int t   = threadIdx.x;
    __shared__ float red[8];

    float4 x = *(const float4*)&X[row * EDIM + t * 4];
    float s = x.x + x.y + x.z + x.w;
#pragma unroll
    for (int ofs = 16; ofs; ofs >>= 1) s += __shfl_xor_sync(0xffffffffu, s, ofs);
    if ((t & 31) == 0) red[t >> 5] = s;
    __syncthreads();
    float tot = 0.0f;
#pragma unroll
    for (int i = 0; i < 8; i++) tot += red[i];
    float mu = tot * (1.0f / 1024.0f);

    float d0 = x.x - mu, d1 = x.y - mu, d2 = x.z - mu, d3 = x.w - mu;
    float sq = d0 * d0 + d1 * d1 + d2 * d2 + d3 * d3;
    __syncthreads();
#pragma unroll
    for (int ofs = 16; ofs; ofs >>= 1) sq += __shfl_xor_sync(0xffffffffu, sq, ofs);
    if ((t & 31) == 0) red[t >> 5] = sq;
    __syncthreads();
    float vtot = 0.0f;
#pragma unroll
    for (int i = 0; i < 8; i++) vtot += red[i];
    float inv = rsqrtf(vtot * (1.0f / 1024.0f) + 1e-5f);

    float4 g  = *(const float4*)&gam[t * 4];
    float4 be = *(const float4*)&bet[t * 4];
    float4 o4;
    o4.x = d0 * inv * g.x + be.x;
    o4.y = d1 * inv * g.y + be.y;
    o4.z = d2 * inv * g.z + be.z;
    o4.w = d3 * inv * g.w + be.w;
    *(float4*)&out[row * EDIM + t * 4] = o4;
}

// ============================================================================
extern "C" void kernel_launch(void* const* d_in, const int* in_sizes, int n_in,
                              void* d_out, int out_size)
{
    const float* query = (const float*)d_in[0];
    const float* key   = (const float*)d_in[1];
    const float* value = (const float*)d_in[2];
    const int*   mask  = (const int*)d_in[3];
    const float* Wq    = (const float*)d_in[4];
    const float* bq    = (const float*)d_in[5];
    const float* Wk    = (const float*)d_in[6];
    const float* bk    = (const float*)d_in[7];
    const float* Wv    = (const float*)d_in[8];
    const float* bv    = (const float*)d_in[9];
    const float* Wo    = (const float*)d_in[10];
    const float* bo    = (const float*)d_in[11];
    const float* gamma = (const float*)d_in[12];
    const float* beta  = (const float*)d_in[13];
    float* out = (float*)d_out;

    __half *hx, *hw, *qh, *kh, *vh, *atth;
    float* go;
    cudaGetSymbolAddress((void**)&hx,   g_hx);
    cudaGetSymbolAddress((void**)&hw,   g_hw);
    cudaGetSymbolAddress((void**)&qh,   g_qh);
    cudaGetSymbolAddress((void**)&kh,   g_kh);
    cudaGetSymbolAddress((void**)&vh,   g_vh);
    cudaGetSymbolAddress((void**)&atth, g_atth);
    cudaGetSymbolAddress((void**)&go,   g_o);

    const size_t ACT = (size_t)MROWS * EDIM;
    const size_t WSZ = (size_t)EDIM * EDIM;

    cudaFuncSetAttribute(gemm_h,
                         cudaFuncAttributeMaxDynamicSharedMemorySize, GEMMH_SMEM);
    cudaFuncSetAttribute(gemm_h3,
                         cudaFuncAttributeMaxDynamicSharedMemorySize, GEMMH_SMEM);
    cudaFuncSetAttribute(attn_h,
                         cudaFuncAttributeMaxDynamicSharedMemorySize, ATTNH_SMEM);

    // fp32 -> fp16 conversion (MLP=4)
    CvtArgs ca;
    ca.x[0] = query; ca.x[1] = key; ca.x[2] = value;
    ca.x[3] = Wq; ca.x[4] = Wk; ca.x[5] = Wv; ca.x[6] = Wo;
    ca.y[0] = hx;           ca.y[1] = hx + ACT;   ca.y[2] = hx + 2 * ACT;
    ca.y[3] = hw;           ca.y[4] = hw + WSZ;
    ca.y[5] = hw + 2 * WSZ; ca.y[6] = hw + 3 * WSZ;
    dim3 gc(CVT_GRID_X, 7);
    cvt7_kernel<<<gc, 256>>>(ca);

    // batched QKV projections
    G3Args g3;
    g3.A[0] = hx;           g3.A[1] = hx + ACT;   g3.A[2] = hx + 2 * ACT;
    g3.W[0] = hw;           g3.W[1] = hw + WSZ;   g3.W[2] = hw + 2 * WSZ;
    g3.bias[0] = bq; g3.bias[1] = bk; g3.bias[2] = bv;
    g3.C[0] = qh; g3.C[1] = kh; g3.C[2] = vh;
    g3.oscale[0] = 0.125f; g3.oscale[1] = 1.0f; g3.oscale[2] = 1.0f;
    dim3 gg3(EDIM / 128, MROWS / 128, 3);   // (8, 32, 3)
    gemm_h3<<<gg3, 256, GEMMH_SMEM>>>(g3);

    dim3 ga(TLEN / 64, BATCH * NHEAD);      // (16, 64)
    attn_h<<<ga, 256, ATTNH_SMEM>>>(mask);

    dim3 gg(EDIM / 128, MROWS / 128);       // (8, 32)
    gemm_h<<<gg, 256, GEMMH_SMEM>>>(atth, hw + 3 * WSZ, bo, go, nullptr, 1.0f);

    ln_kernel<<<MROWS, 256>>>(go, gamma, beta, out);
}

// round 13
// speedup vs baseline: 1.1512x; 1.0630x over previous
#include <cuda_runtime.h>
#include <cuda_fp16.h>
#include <math.h>
#include <stdint.h>

#define EDIM 1024
#define TLEN 1024
#define BATCH 4
#define NHEAD 16
#define HDIM 64
#define MROWS (BATCH * TLEN)   // 4096

// ---------------- scratch (device globals: no runtime allocation) ----------
__device__ __align__(128) __half g_hx[3][(size_t)MROWS * EDIM]; // q,k,v inputs fp16
__device__ __align__(128) __half g_hw[4][(size_t)EDIM * EDIM];  // Wq,Wk,Wv,Wo fp16
__device__ __align__(128) __half g_qh[(size_t)MROWS * EDIM];    // Q proj (x0.125)
__device__ __align__(128) __half g_kh[(size_t)MROWS * EDIM];
__device__ __align__(128) __half g_vh[(size_t)MROWS * EDIM];
__device__ __align__(128) __half g_atth[(size_t)MROWS * EDIM];
__device__ __align__(128) float  g_o[(size_t)MROWS * EDIM];

// ============================ helpers =======================================
__device__ __forceinline__ uint32_t smem_u32(const void* p) {
    uint32_t a;
    asm("{ .reg .u64 t; cvta.to.shared.u64 t, %1; cvt.u32.u64 %0, t; }"
        : "=r"(a) : "l"(p));
    return a;
}
__device__ __forceinline__ void cp_async16(uint32_t dst, const void* src) {
    asm volatile("cp.async.cg.shared.global [%0], [%1], 16;"
                 :: "r"(dst), "l"(src));
}
#define CP_COMMIT() asm volatile("cp.async.commit_group;" ::: "memory")
#define CP_WAIT0()  asm volatile("cp.async.wait_group 0;" ::: "memory")
#define CP_WAIT1()  asm volatile("cp.async.wait_group 1;" ::: "memory")

__device__ __forceinline__ void mma_f16(float* d, const uint32_t* a,
                                        const uint32_t* b) {
    asm volatile(
        "mma.sync.aligned.m16n8k16.row.col.f32.f16.f16.f32 "
        "{%0,%1,%2,%3}, {%4,%5,%6,%7}, {%8,%9}, {%0,%1,%2,%3};"
        : "+f"(d[0]), "+f"(d[1]), "+f"(d[2]), "+f"(d[3])
        : "r"(a[0]), "r"(a[1]), "r"(a[2]), "r"(a[3]),
          "r"(b[0]), "r"(b[1]));
}
__device__ __forceinline__ void ldsm_x4(uint32_t* r, uint32_t addr) {
    asm volatile("ldmatrix.sync.aligned.m8n8.x4.shared.b16 {%0,%1,%2,%3}, [%4];"
                 : "=r"(r[0]), "=r"(r[1]), "=r"(r[2]), "=r"(r[3]) : "r"(addr));
}
__device__ __forceinline__ void ldsm_x2(uint32_t* r, uint32_t addr) {
    asm volatile("ldmatrix.sync.aligned.m8n8.x2.shared.b16 {%0,%1}, [%2];"
                 : "=r"(r[0]), "=r"(r[1]) : "r"(addr));
}
__device__ __forceinline__ void ldsm_x2_t(uint32_t* r, uint32_t addr) {
    asm volatile("ldmatrix.sync.aligned.m8n8.x2.trans.shared.b16 {%0,%1}, [%2];"
                 : "=r"(r[0]), "=r"(r[1]) : "r"(addr));
}
__device__ __forceinline__ uint32_t h2pack(float a, float b) {
    __half2 h = __floats2half2_rn(a, b);
    return *(uint32_t*)&h;
}

// ============================================================================
// Batched fp32 -> fp16 convert, MLP=4.
// ============================================================================
#define CVT_GRID_X 1024
struct CvtArgs { const float* x[7]; __half* y[7]; };

__global__ __launch_bounds__(256) void cvt7_kernel(CvtArgs args)
{
    const int z = blockIdx.y;
    const float* __restrict__ x = args.x[z];
    __half* __restrict__ y = args.y[z];
    const int i = blockIdx.x * 256 + threadIdx.x;
    const int stride = CVT_GRID_X * 256;   // 262144

    if (z < 3) {
        float4 v0 = *(const float4*)&x[(size_t)(i + 0 * stride) * 4];
        float4 v1 = *(const float4*)&x[(size_t)(i + 1 * stride) * 4];
        float4 v2 = *(const float4*)&x[(size_t)(i + 2 * stride) * 4];
        float4 v3 = *(const float4*)&x[(size_t)(i + 3 * stride) * 4];
#define CVT_ST(v, ii) do {                                        \
        __half2 h0 = __floats2half2_rn((v).x, (v).y);             \
        __half2 h1 = __floats2half2_rn((v).z, (v).w);             \
        uint2 oo = make_uint2(*(uint32_t*)&h0, *(uint32_t*)&h1);  \
        *(uint2*)&y[(size_t)(ii) * 4] = oo; } while (0)
        CVT_ST(v0, i + 0 * stride);
        CVT_ST(v1, i + 1 * stride);
        CVT_ST(v2, i + 2 * stride);
        CVT_ST(v3, i + 3 * stride);
    } else {
        float4 v0 = *(const float4*)&x[(size_t)i * 4];
        CVT_ST(v0, i);
#undef CVT_ST
    }
}

// ============================================================================
// fp16 GEMM core (proven R11). 128x128 tile, BK=64, 3-stage cp.async,
// 8 warps 2Mx4N, pairwise ldmatrix.x4 B fragments.
// ============================================================================
#define HSTR 72
#define HTILEB (128 * HSTR * 2)       // 18432 B
#define GEMMH_SMEM (3 * 2 * HTILEB)   // 110592 B

__device__ __forceinline__ void gemm_h_body(
    const __half* __restrict__ A, const __half* __restrict__ W,
    const float* __restrict__ bias, float* __restrict__ Cf,
    __half* __restrict__ Ch, float oscale, char* smraw)
{
    const uint32_t sm0 = smem_u32(smraw);

    const int t    = threadIdx.x;
    const int wid  = t >> 5;
    const int lane = t & 31;
    const int grp  = lane >> 2;
    const int tig  = lane & 3;
    const int wm   = (wid >> 2) * 64;
    const int wn   = (wid & 3) * 32;
    const int m0   = blockIdx.y * 128;
    const int n0   = blockIdx.x * 128;

    const int lr = t >> 1;
    const int cc = (t & 1) * 4;

    const int laRow = lane & 15, laCol = (lane >> 4) * 8;
    const int pbRow = ((lane >> 4) & 1) * 8 + (lane & 7);
    const int pbCol = ((lane >> 3) & 1) * 8;

    float acc[4][4][4];
#pragma unroll
    for (int mi = 0; mi < 4; mi++)
#pragma unroll
        for (int nj = 0; nj < 4; nj++)
#pragma unroll
            for (int q = 0; q < 4; q++) acc[mi][nj][q] = 0.0f;

#pragma unroll
    for (int s = 0; s < 2; s++) {
        uint32_t dA = sm0 + s * 2 * HTILEB;
        uint32_t dB = dA + HTILEB;
        const int k0 = s * 64;
#pragma unroll
        for (int j = 0; j < 4; j++) {
            int c = cc + j;
            cp_async16(dA + (lr * HSTR + c * 8) * 2,
                       A + (size_t)(m0 + lr) * EDIM + k0 + c * 8);
            cp_async16(dB + (lr * HSTR + c * 8) * 2,
                       W + (size_t)(n0 + lr) * EDIM + k0 + c * 8);
        }
        CP_COMMIT();
    }

    const int NIT = EDIM / 64;   // 16
    int stage = 0;
    for (int it = 0; it < NIT; it++) {
        if (it + 1 < NIT) { CP_WAIT1(); } else { CP_WAIT0(); }
        __syncthreads();

        if (it + 2 < NIT) {
            int ps = stage + 2; if (ps >= 3) ps -= 3;
            const int k0 = (it + 2) * 64;
            uint32_t dA = sm0 + ps * 2 * HTILEB;
            uint32_t dB = dA + HTILEB;
#pragma unroll
            for (int j = 0; j < 4; j++) {
                int c = cc + j;
                cp_async16(dA + (lr * HSTR + c * 8) * 2,
                           A + (size_t)(m0 + lr) * EDIM + k0 + c * 8);
                cp_async16(dB + (lr * HSTR + c * 8) * 2,
                           W + (size_t)(n0 + lr) * EDIM + k0 + c * 8);
            }
            CP_COMMIT();
        }

        const uint32_t aS = sm0 + stage * 2 * HTILEB;
        const uint32_t bS = aS + HTILEB;

#pragma unroll
        for (int ks = 0; ks < 4; ks++) {
            uint32_t af[4][4], bf[4][2];
#pragma unroll
            for (int mi = 0; mi < 4; mi++)
                ldsm_x4(af[mi], aS + ((wm + mi * 16 + laRow) * HSTR
                                      + ks * 16 + laCol) * 2);
#pragma unroll
            for (int njp = 0; njp < 2; njp++) {
                uint32_t r4[4];
                ldsm_x4(r4, bS + ((wn + njp * 16 + pbRow) * HSTR
                                  + ks * 16 + pbCol) * 2);
                bf[2 * njp][0] = r4[0]; bf[2 * njp][1] = r4[1];
                bf[2 * njp + 1][0] = r4[2]; bf[2 * njp + 1][1] = r4[3];
            }
#pragma unroll
            for (int mi = 0; mi < 4; mi++)
#pragma unroll
                for (int nj = 0; nj < 4; nj++)
                    mma_f16(acc[mi][nj], af[mi], bf[nj]);
        }

        if (++stage >= 3) stage = 0;
    }

#pragma unroll
    for (int mi = 0; mi < 4; mi++) {
        int rg = m0 + wm + mi * 16 + grp;
#pragma unroll
        for (int nj = 0; nj < 4; nj++) {
            int cg = n0 + wn + nj * 8 + tig * 2;
            float2 bv = *(const float2*)&bias[cg];
            float o00 = (acc[mi][nj][0] + bv.x) * oscale;
            float o01 = (acc[mi][nj][1] + bv.y) * oscale;
            float o10 = (acc[mi][nj][2] + bv.x) * oscale;
            float o11 = (acc[mi][nj][3] + bv.y) * oscale;
            if (Ch) {
                *(__half2*)&Ch[(size_t)rg * EDIM + cg]       = __floats2half2_rn(o00, o01);
                *(__half2*)&Ch[(size_t)(rg + 8) * EDIM + cg] = __floats2half2_rn(o10, o11);
            } else {
                *(float2*)&Cf[(size_t)rg * EDIM + cg]       = make_float2(o00, o01);
                *(float2*)&Cf[(size_t)(rg + 8) * EDIM + cg] = make_float2(o10, o11);
            }
        }
    }
}

struct G3Args {
    const __half* A[3]; const __half* W[3];
    const float* bias[3]; __half* C[3]; float oscale[3];
};

__global__ __launch_bounds__(256, 2) void gemm_h3(G3Args args)
{
    extern __shared__ char smraw[];
    const int z = blockIdx.z;
    gemm_h_body(args.A[z], args.W[z], args.bias[z], nullptr,
                args.C[z], args.oscale[z], smraw);
}

__global__ __launch_bounds__(256, 2) void gemm_h(
    const __half* __restrict__ A, const __half* __restrict__ W,
    const float* __restrict__ bias, float* __restrict__ Cf,
    __half* __restrict__ Ch, float oscale)
{
    extern __shared__ char smraw[];
    gemm_h_body(A, W, bias, Cf, Ch, oscale, smraw);
}

// ============================================================================
// FA2-style fp16 flash attention: 64 q x (b*h) per block, 128 threads
// (4 warps x 16 q-rows, each warp spans the FULL 64-k stripe).
// P stays in registers (S-accum layout == PV A-fragment layout).
// Stats entirely in registers via tig-shuffles. 1 barrier per tile.
// smem: Q 64x72h, K 2x64x72h, V 2x64x72h = 46080 B.
// ============================================================================
#define ATTNH_SMEM 46080

__global__ __launch_bounds__(128) void attn_h(const int* __restrict__ mask)
{
    extern __shared__ char smraw[];
    const uint32_t sQ = smem_u32(smraw);
    const uint32_t sK = sQ + 9216;
    const uint32_t sV = sQ + 27648;

    const int t    = threadIdx.x;
    const int wid  = t >> 5;          // 0..3
    const int lane = t & 31;
    const int grp  = lane >> 2;
    const int tig  = lane & 3;
    const int wm   = wid * 16;
    const int q0   = blockIdx.x * 64;
    const int bh   = blockIdx.y;
    const int b    = bh >> 4;
    const int h    = bh & 15;
    const int hofs = h * HDIM;

    const int lrow = t >> 1;          // loader row 0..63
    const int lcc  = (t & 1) * 4;     // 4 chunks of 16B each

    const int laRow = lane & 15, laCol = (lane >> 4) * 8;
    const int pbRow = ((lane >> 4) & 1) * 8 + (lane & 7);
    const int pbCol = ((lane >> 3) & 1) * 8;

    // ---- prologue: Q + K/V tile 0 ----
#pragma unroll
    for (int j = 0; j < 4; j++) {
        int c = lcc + j;
        size_t gq = (size_t)(b * TLEN + q0 + lrow) * EDIM + hofs + c * 8;
        cp_async16(sQ + (lrow * HSTR + c * 8) * 2, g_qh + gq);
        size_t gkv = (size_t)(b * TLEN + lrow) * EDIM + hofs + c * 8;
        cp_async16(sK + (lrow * HSTR + c * 8) * 2, g_kh + gkv);
        cp_async16(sV + (lrow * HSTR + c * 8) * 2, g_vh + gkv);
    }
    CP_COMMIT();

    const int r0 = wm + grp;
    const int r1 = wm + grp + 8;

    uint32_t qf[4][4];                 // Q fragments, hoisted (constant)
    float o[8][4];
#pragma unroll
    for (int nf = 0; nf < 8; nf++)
#pragma unroll
        for (int q = 0; q < 4; q++) o[nf][q] = 0.0f;
    float mo0 = -1e30f, mo1 = -1e30f, L0 = 0.0f, L1 = 0.0f;

    for (int kt = 0; kt < TLEN / 64; kt++) {
        const int cur = kt & 1;
        CP_WAIT0();
        __syncthreads();

        if (kt == 0) {
#pragma unroll
            for (int ks = 0; ks < 4; ks++)
                ldsm_x4(qf[ks], sQ + ((wm + laRow) * HSTR + ks * 16 + laCol) * 2);
        }

        if (kt + 1 < TLEN / 64) {
            const int nb = cur ^ 1;
            uint32_t kd = sK + nb * 9216;
            uint32_t vd = sV + nb * 9216;
#pragma unroll
            for (int j = 0; j < 4; j++) {
                int c = lcc + j;
                size_t gkv = (size_t)(b * TLEN + (kt + 1) * 64 + lrow) * EDIM + hofs + c * 8;
                cp_async16(kd + (lrow * HSTR + c * 8) * 2, g_kh + gkv);
                cp_async16(vd + (lrow * HSTR + c * 8) * 2, g_vh + gkv);
            }
            CP_COMMIT();
        }

        const uint32_t kB = sK + cur * 9216;
        const uint32_t vB = sV + cur * 9216;

        // ---- hoisted mask loads: rows r0/r1, cols nf*8 + 2tig ----
        int2 mreg0[8], mreg1[8];
        const size_t mbase = (size_t)(b * TLEN + q0 + r0) * TLEN + kt * 64 + tig * 2;
#pragma unroll
        for (int nf = 0; nf < 8; nf++) {
            mreg0[nf] = *(const int2*)&mask[mbase + nf * 8];
            mreg1[nf] = *(const int2*)&mask[mbase + (size_t)8 * TLEN + nf * 8];
        }

        // ---- S = Q @ K^T over the full 64-k stripe ----
        float s[8][4];
#pragma unroll
        for (int nf = 0; nf < 8; nf++)
#pragma unroll
            for (int q = 0; q < 4; q++) s[nf][q] = 0.0f;

#pragma unroll
        for (int ks = 0; ks < 4; ks++) {
            uint32_t bf[8][2];
#pragma unroll
            for (int njp = 0; njp < 4; njp++) {
                uint32_t r4[4];
                ldsm_x4(r4, kB + ((njp * 16 + pbRow) * HSTR + ks * 16 + pbCol) * 2);
                bf[2 * njp][0] = r4[0]; bf[2 * njp][1] = r4[1];
                bf[2 * njp + 1][0] = r4[2]; bf[2 * njp + 1][1] = r4[3];
            }
#pragma unroll
            for (int nf = 0; nf < 8; nf++)
                mma_f16(s[nf], qf[ks], bf[nf]);
        }

        // ---- mask + in-register row max (tig shuffles) ----
        float mx0 = -1e30f, mx1 = -1e30f;
#pragma unroll
        for (int nf = 0; nf < 8; nf++) {
            s[nf][0] = (mreg0[nf].x == 0) ? -1.0e9f : s[nf][0];
            s[nf][1] = (mreg0[nf].y == 0) ? -1.0e9f : s[nf][1];
            s[nf][2] = (mreg1[nf].x == 0) ? -1.0e9f : s[nf][2];
            s[nf][3] = (mreg1[nf].y == 0) ? -1.0e9f : s[nf][3];
            mx0 = fmaxf(mx0, fmaxf(s[nf][0], s[nf][1]));
            mx1 = fmaxf(mx1, fmaxf(s[nf][2], s[nf][3]));
        }
        mx0 = fmaxf(mx0, __shfl_xor_sync(0xffffffffu, mx0, 1));
        mx0 = fmaxf(mx0, __shfl_xor_sync(0xffffffffu, mx0, 2));
        mx1 = fmaxf(mx1, __shfl_xor_sync(0xffffffffu, mx1, 1));
        mx1 = fmaxf(mx1, __shfl_xor_sync(0xffffffffu, mx1, 2));

        float mN0 = fmaxf(mo0, mx0);
        float mN1 = fmaxf(mo1, mx1);
        float a0  = __expf(mo0 - mN0);
        float a1  = __expf(mo1 - mN1);
        mo0 = mN0; mo1 = mN1;

        // ---- P = exp(S - m), packed straight into PV A-fragments ----
        uint32_t pp0[8], pp1[8];
        float sum0 = 0.0f, sum1 = 0.0f;
#pragma unroll
        for (int nf = 0; nf < 8; nf++) {
            float p00 = __expf(s[nf][0] - mN0);
            float p01 = __expf(s[nf][1] - mN0);
            float p10 = __expf(s[nf][2] - mN1);
            float p11 = __expf(s[nf][3] - mN1);
            sum0 += p00 + p01;
            sum1 += p10 + p11;
            pp0[nf] = h2pack(p00, p01);
            pp1[nf] = h2pack(p10, p11);
        }
        sum0 += __shfl_xor_sync(0xffffffffu, sum0, 1);
        sum0 += __shfl_xor_sync(0xffffffffu, sum0, 2);
        sum1 += __shfl_xor_sync(0xffffffffu, sum1, 1);
        sum1 += __shfl_xor_sync(0xffffffffu, sum1, 2);
        L0 = L0 * a0 + sum0;
        L1 = L1 * a1 + sum1;

        // ---- rescale O ----
#pragma unroll
        for (int nf = 0; nf < 8; nf++) {
            o[nf][0] *= a0; o[nf][1] *= a0;
            o[nf][2] *= a1; o[nf][3] *= a1;
        }

        // ---- O += P @ V (P from registers; V [k][d] via ldmatrix.trans) ----
#pragma unroll
        for (int ks = 0; ks < 4; ks++) {
            uint32_t af[4];
            af[0] = pp0[2 * ks];
            af[1] = pp1[2 * ks];
            af[2] = pp0[2 * ks + 1];
            af[3] = pp1[2 * ks + 1];
#pragma unroll
            for (int nf = 0; nf < 8; nf++) {
                uint32_t bf[2];
                ldsm_x2_t(bf, vB + ((ks * 16 + laRow) * HSTR + nf * 8) * 2);
                mma_f16(o[nf], af, bf);
            }
        }
    }

    // ---- normalize + write (L already consistent across tig lanes) ----
    const float linv0 = 1.0f / L0;
    const float linv1 = 1.0f / L1;
    const size_t orow0 = (size_t)(b * TLEN + q0 + r0) * EDIM + hofs;
    const size_t orow1 = (size_t)(b * TLEN + q0 + r1) * EDIM + hofs;
#pragma unroll
    for (int nf = 0; nf < 8; nf++) {
        int col = nf * 8 + tig * 2;
        *(__half2*)&g_atth[orow0 + col] =
            __floats2half2_rn(o[nf][0] * linv0, o[nf][1] * linv0);
        *(__half2*)&g_atth[orow1 + col] =
            __floats2half2_rn(o[nf][2] * linv1, o[nf][3] * linv1);
    }
}

// ============================================================================
// LayerNorm over E=1024, one block (256 threads) per row.
// ============================================================================
__global__ __launch_bounds__(256) void ln_kernel(
    const float* __restrict__ X, const float* __restrict__ gam,
    const float* __restrict__ bet, float* __restrict__ out)
{
    const int row = blockIdx.x;
    const int t   = threadIdx.x;
    __shared__ float red[8];

    float4 x = *(const float4*)&X[row * EDIM + t * 4];
    float s = x.x + x.y + x.z + x.w;
#pragma unroll
    for (int ofs = 16; ofs; ofs >>= 1) s += __shfl_xor_sync(0xffffffffu, s, ofs);
    if ((t & 31) == 0) red[t >> 5] = s;
    __syncthreads();
    float tot = 0.0f;
#pragma unroll
    for (int i = 0; i < 8; i++) tot += red[i];
    float mu = tot * (1.0f / 1024.0f);

    float d0 = x.x - mu, d1 = x.y - mu, d2 = x.z - mu, d3 = x.w - mu;
    float sq = d0 * d0 + d1 * d1 + d2 * d2 + d3 * d3;
    __syncthreads();
#pragma unroll
    for (int ofs = 16; ofs; ofs >>= 1) sq += __shfl_xor_sync(0xffffffffu, sq, ofs);
    if ((t & 31) == 0) red[t >> 5] = sq;
    __syncthreads();
    float vtot = 0.0f;
#pragma unroll
    for (int i = 0; i < 8; i++) vtot += red[i];
    float inv = rsqrtf(vtot * (1.0f / 1024.0f) + 1e-5f);

    float4 g  = *(const float4*)&gam[t * 4];
    float4 be = *(const float4*)&bet[t * 4];
    float4 o4;
    o4.x = d0 * inv * g.x + be.x;
    o4.y = d1 * inv * g.y + be.y;
    o4.z = d2 * inv * g.z + be.z;
    o4.w = d3 * inv * g.w + be.w;
    *(float4*)&out[row * EDIM + t * 4] = o4;
}

// ============================================================================
extern "C" void kernel_launch(void* const* d_in, const int* in_sizes, int n_in,
                              void* d_out, int out_size)
{
    const float* query = (const float*)d_in[0];
    const float* key   = (const float*)d_in[1];
    const float* value = (const float*)d_in[2];
    const int*   mask  = (const int*)d_in[3];
    const float* Wq    = (const float*)d_in[4];
    const float* bq    = (const float*)d_in[5];
    const float* Wk    = (const float*)d_in[6];
    const float* bk    = (const float*)d_in[7];
    const float* Wv    = (const float*)d_in[8];
    const float* bv    = (const float*)d_in[9];
    const float* Wo    = (const float*)d_in[10];
    const float* bo    = (const float*)d_in[11];
    const float* gamma = (const float*)d_in[12];
    const float* beta  = (const float*)d_in[13];
    float* out = (float*)d_out;

    __half *hx, *hw, *qh, *kh, *vh, *atth;
    float* go;
    cudaGetSymbolAddress((void**)&hx,   g_hx);
    cudaGetSymbolAddress((void**)&hw,   g_hw);
    cudaGetSymbolAddress((void**)&qh,   g_qh);
    cudaGetSymbolAddress((void**)&kh,   g_kh);
    cudaGetSymbolAddress((void**)&vh,   g_vh);
    cudaGetSymbolAddress((void**)&atth, g_atth);
    cudaGetSymbolAddress((void**)&go,   g_o);

    const size_t ACT = (size_t)MROWS * EDIM;
    const size_t WSZ = (size_t)EDIM * EDIM;

    cudaFuncSetAttribute(gemm_h,
                         cudaFuncAttributeMaxDynamicSharedMemorySize, GEMMH_SMEM);
    cudaFuncSetAttribute(gemm_h3,
                         cudaFuncAttributeMaxDynamicSharedMemorySize, GEMMH_SMEM);
    cudaFuncSetAttribute(attn_h,
                         cudaFuncAttributeMaxDynamicSharedMemorySize, ATTNH_SMEM);

    // fp32 -> fp16 conversion (MLP=4)
    CvtArgs ca;
    ca.x[0] = query; ca.x[1] = key; ca.x[2] = value;
    ca.x[3] = Wq; ca.x[4] = Wk; ca.x[5] = Wv; ca.x[6] = Wo;
    ca.y[0] = hx;           ca.y[1] = hx + ACT;   ca.y[2] = hx + 2 * ACT;
    ca.y[3] = hw;           ca.y[4] = hw + WSZ;
    ca.y[5] = hw + 2 * WSZ; ca.y[6] = hw + 3 * WSZ;
    dim3 gc(CVT_GRID_X, 7);
    cvt7_kernel<<<gc, 256>>>(ca);

    // batched QKV projections
    G3Args g3;
    g3.A[0] = hx;           g3.A[1] = hx + ACT;   g3.A[2] = hx + 2 * ACT;
    g3.W[0] = hw;           g3.W[1] = hw + WSZ;   g3.W[2] = hw + 2 * WSZ;
    g3.bias[0] = bq; g3.bias[1] = bk; g3.bias[2] = bv;
    g3.C[0] = qh; g3.C[1] = kh; g3.C[2] = vh;
    g3.oscale[0] = 0.125f; g3.oscale[1] = 1.0f; g3.oscale[2] = 1.0f;
    dim3 gg3(EDIM / 128, MROWS / 128, 3);   // (8, 32, 3)
    gemm_h3<<<gg3, 256, GEMMH_SMEM>>>(g3);

    dim3 ga(TLEN / 64, BATCH * NHEAD);      // (16, 64)
    attn_h<<<ga, 128, ATTNH_SMEM>>>(mask);

    dim3 gg(EDIM / 128, MROWS / 128);       // (8, 32)
    gemm_h<<<gg, 256, GEMMH_SMEM>>>(atth, hw + 3 * WSZ, bo, go, nullptr, 1.0f);

    ln_kernel<<<MROWS, 256>>>(go, gamma, beta, out);
}

// round 14
// speedup vs baseline: 1.1795x; 1.0245x over previous
#include <cuda_runtime.h>
#include <cuda_fp16.h>
#include <math.h>
#include <stdint.h>

#define EDIM 1024
#define TLEN 1024
#define BATCH 4
#define NHEAD 16
#define HDIM 64
#define MROWS (BATCH * TLEN)   // 4096

// ---------------- scratch (device globals: no runtime allocation) ----------
__device__ __align__(128) __half g_hx[3][(size_t)MROWS * EDIM]; // q,k,v inputs fp16
__device__ __align__(128) __half g_hw[4][(size_t)EDIM * EDIM];  // Wq,Wk,Wv,Wo fp16
__device__ __align__(128) __half g_qh[(size_t)MROWS * EDIM];    // Q proj (x0.125)
__device__ __align__(128) __half g_kh[(size_t)MROWS * EDIM];
__device__ __align__(128) __half g_vh[(size_t)MROWS * EDIM];
__device__ __align__(128) __half g_atth[(size_t)MROWS * EDIM];
__device__ __align__(128) float  g_o[(size_t)MROWS * EDIM];
__device__ __align__(128) unsigned long long g_mbits[(size_t)MROWS * 16];

// ============================ helpers =======================================
__device__ __forceinline__ uint32_t smem_u32(const void* p) {
    uint32_t a;
    asm("{ .reg .u64 t; cvta.to.shared.u64 t, %1; cvt.u32.u64 %0, t; }"
        : "=r"(a) : "l"(p));
    return a;
}
__device__ __forceinline__ void cp_async16(uint32_t dst, const void* src) {
    asm volatile("cp.async.cg.shared.global [%0], [%1], 16;"
                 :: "r"(dst), "l"(src));
}
#define CP_COMMIT() asm volatile("cp.async.commit_group;" ::: "memory")
#define CP_WAIT0()  asm volatile("cp.async.wait_group 0;" ::: "memory")
#define CP_WAIT1()  asm volatile("cp.async.wait_group 1;" ::: "memory")

__device__ __forceinline__ void mma_f16(float* d, const uint32_t* a,
                                        const uint32_t* b) {
    asm volatile(
        "mma.sync.aligned.m16n8k16.row.col.f32.f16.f16.f32 "
        "{%0,%1,%2,%3}, {%4,%5,%6,%7}, {%8,%9}, {%0,%1,%2,%3};"
        : "+f"(d[0]), "+f"(d[1]), "+f"(d[2]), "+f"(d[3])
        : "r"(a[0]), "r"(a[1]), "r"(a[2]), "r"(a[3]),
          "r"(b[0]), "r"(b[1]));
}
__device__ __forceinline__ void ldsm_x4(uint32_t* r, uint32_t addr) {
    asm volatile("ldmatrix.sync.aligned.m8n8.x4.shared.b16 {%0,%1,%2,%3}, [%4];"
                 : "=r"(r[0]), "=r"(r[1]), "=r"(r[2]), "=r"(r[3]) : "r"(addr));
}
__device__ __forceinline__ void ldsm_x4_t(uint32_t* r, uint32_t addr) {
    asm volatile("ldmatrix.sync.aligned.m8n8.x4.trans.shared.b16 {%0,%1,%2,%3}, [%4];"
                 : "=r"(r[0]), "=r"(r[1]), "=r"(r[2]), "=r"(r[3]) : "r"(addr));
}
__device__ __forceinline__ uint32_t h2pack(float a, float b) {
    __half2 h = __floats2half2_rn(a, b);
    return *(uint32_t*)&h;
}

// ============================================================================
// Mask bit-pack: mbits[(b*T+q)*16 + kt] bit j = (mask[b,q,kt*64+j] != 0)
// ============================================================================
__global__ __launch_bounds__(256) void maskpack_kernel(
    const int* __restrict__ mask, unsigned long long* __restrict__ bits)
{
    const int id  = blockIdx.x * 256 + threadIdx.x;  // 65536
    const int row = id >> 4;
    const int kt  = id & 15;
    const int4* p = (const int4*)(mask + (size_t)row * TLEN + kt * 64);
    unsigned long long w = 0;
#pragma unroll
    for (int c = 0; c < 16; c++) {
        int4 v = p[c];
        w |= (unsigned long long)(v.x != 0) << (c * 4 + 0);
        w |= (unsigned long long)(v.y != 0) << (c * 4 + 1);
        w |= (unsigned long long)(v.z != 0) << (c * 4 + 2);
        w |= (unsigned long long)(v.w != 0) << (c * 4 + 3);
    }
    bits[(size_t)row * 16 + kt] = w;
}

// ============================================================================
// Batched fp32 -> fp16 convert, MLP=4.
// ============================================================================
#define CVT_GRID_X 1024
struct CvtArgs { const float* x[7]; __half* y[7]; };

__global__ __launch_bounds__(256) void cvt7_kernel(CvtArgs args)
{
    const int z = blockIdx.y;
    const float* __restrict__ x = args.x[z];
    __half* __restrict__ y = args.y[z];
    const int i = blockIdx.x * 256 + threadIdx.x;
    const int stride = CVT_GRID_X * 256;   // 262144

    if (z < 3) {
        float4 v0 = *(const float4*)&x[(size_t)(i + 0 * stride) * 4];
        float4 v1 = *(const float4*)&x[(size_t)(i + 1 * stride) * 4];
        float4 v2 = *(const float4*)&x[(size_t)(i + 2 * stride) * 4];
        float4 v3 = *(const float4*)&x[(size_t)(i + 3 * stride) * 4];
#define CVT_ST(v, ii) do {                                        \
        __half2 h0 = __floats2half2_rn((v).x, (v).y);             \
        __half2 h1 = __floats2half2_rn((v).z, (v).w);             \
        uint2 oo = make_uint2(*(uint32_t*)&h0, *(uint32_t*)&h1);  \
        *(uint2*)&y[(size_t)(ii) * 4] = oo; } while (0)
        CVT_ST(v0, i + 0 * stride);
        CVT_ST(v1, i + 1 * stride);
        CVT_ST(v2, i + 2 * stride);
        CVT_ST(v3, i + 3 * stride);
    } else {
        float4 v0 = *(const float4*)&x[(size_t)i * 4];
        CVT_ST(v0, i);
#undef CVT_ST
    }
}

// ============================================================================
// fp16 GEMM core (proven R11). 128x128 tile, BK=64, 3-stage cp.async,
// 8 warps 2Mx4N, pairwise ldmatrix.x4 B fragments.
// ============================================================================
#define HSTR 72
#define HTILEB (128 * HSTR * 2)       // 18432 B
#define GEMMH_SMEM (3 * 2 * HTILEB)   // 110592 B

__device__ __forceinline__ void gemm_h_body(
    const __half* __restrict__ A, const __half* __restrict__ W,
    const float* __restrict__ bias, float* __restrict__ Cf,
    __half* __restrict__ Ch, float oscale, char* smraw)
{
    const uint32_t sm0 = smem_u32(smraw);

    const int t    = threadIdx.x;
    const int wid  = t >> 5;
    const int lane = t & 31;
    const int grp  = lane >> 2;
    const int tig  = lane & 3;
    const int wm   = (wid >> 2) * 64;
    const int wn   = (wid & 3) * 32;
    const int m0   = blockIdx.y * 128;
    const int n0   = blockIdx.x * 128;

    const int lr = t >> 1;
    const int cc = (t & 1) * 4;

    const int laRow = lane & 15, laCol = (lane >> 4) * 8;
    const int pbRow = ((lane >> 4) & 1) * 8 + (lane & 7);
    const int pbCol = ((lane >> 3) & 1) * 8;

    float acc[4][4][4];
#pragma unroll
    for (int mi = 0; mi < 4; mi++)
#pragma unroll
        for (int nj = 0; nj < 4; nj++)
#pragma unroll
            for (int q = 0; q < 4; q++) acc[mi][nj][q] = 0.0f;

#pragma unroll
    for (int s = 0; s < 2; s++) {
        uint32_t dA = sm0 + s * 2 * HTILEB;
        uint32_t dB = dA + HTILEB;
        const int k0 = s * 64;
#pragma unroll
        for (int j = 0; j < 4; j++) {
            int c = cc + j;
            cp_async16(dA + (lr * HSTR + c * 8) * 2,
                       A + (size_t)(m0 + lr) * EDIM + k0 + c * 8);
            cp_async16(dB + (lr * HSTR + c * 8) * 2,
                       W + (size_t)(n0 + lr) * EDIM + k0 + c * 8);
        }
        CP_COMMIT();
    }

    const int NIT = EDIM / 64;   // 16
    int stage = 0;
    for (int it = 0; it < NIT; it++) {
        if (it + 1 < NIT) { CP_WAIT1(); } else { CP_WAIT0(); }
        __syncthreads();

        if (it + 2 < NIT) {
            int ps = stage + 2; if (ps >= 3) ps -= 3;
            const int k0 = (it + 2) * 64;
            uint32_t dA = sm0 + ps * 2 * HTILEB;
            uint32_t dB = dA + HTILEB;
#pragma unroll
            for (int j = 0; j < 4; j++) {
                int c = cc + j;
                cp_async16(dA + (lr * HSTR + c * 8) * 2,
                           A + (size_t)(m0 + lr) * EDIM + k0 + c * 8);
                cp_async16(dB + (lr * HSTR + c * 8) * 2,
                           W + (size_t)(n0 + lr) * EDIM + k0 + c * 8);
            }
            CP_COMMIT();
        }

        const uint32_t aS = sm0 + stage * 2 * HTILEB;
        const uint32_t bS = aS + HTILEB;

#pragma unroll
        for (int ks = 0; ks < 4; ks++) {
            uint32_t af[4][4], bf[4][2];
#pragma unroll
            for (int mi = 0; mi < 4; mi++)
                ldsm_x4(af[mi], aS + ((wm + mi * 16 + laRow) * HSTR
                                      + ks * 16 + laCol) * 2);
#pragma unroll
            for (int njp = 0; njp < 2; njp++) {
                uint32_t r4[4];
                ldsm_x4(r4, bS + ((wn + njp * 16 + pbRow) * HSTR
                                  + ks * 16 + pbCol) * 2);
                bf[2 * njp][0] = r4[0]; bf[2 * njp][1] = r4[1];
                bf[2 * njp + 1][0] = r4[2]; bf[2 * njp + 1][1] = r4[3];
            }
#pragma unroll
            for (int mi = 0; mi < 4; mi++)
#pragma unroll
                for (int nj = 0; nj < 4; nj++)
                    mma_f16(acc[mi][nj], af[mi], bf[nj]);
        }

        if (++stage >= 3) stage = 0;
    }

#pragma unroll
    for (int mi = 0; mi < 4; mi++) {
        int rg = m0 + wm + mi * 16 + grp;
#pragma unroll
        for (int nj = 0; nj < 4; nj++) {
            int cg = n0 + wn + nj * 8 + tig * 2;
            float2 bv = *(const float2*)&bias[cg];
            float o00 = (acc[mi][nj][0] + bv.x) * oscale;
            float o01 = (acc[mi][nj][1] + bv.y) * oscale;
            float o10 = (acc[mi][nj][2] + bv.x) * oscale;
            float o11 = (acc[mi][nj][3] + bv.y) * oscale;
            if (Ch) {
                *(__half2*)&Ch[(size_t)rg * EDIM + cg]       = __floats2half2_rn(o00, o01);
                *(__half2*)&Ch[(size_t)(rg + 8) * EDIM + cg] = __floats2half2_rn(o10, o11);
            } else {
                *(float2*)&Cf[(size_t)rg * EDIM + cg]       = make_float2(o00, o01);
                *(float2*)&Cf[(size_t)(rg + 8) * EDIM + cg] = make_float2(o10, o11);
            }
        }
    }
}

struct G3Args {
    const __half* A[3]; const __half* W[3];
    const float* bias[3]; __half* C[3]; float oscale[3];
};

__global__ __launch_bounds__(256, 2) void gemm_h3(G3Args args)
{
    extern __shared__ char smraw[];
    const int z = blockIdx.z;
    gemm_h_body(args.A[z], args.W[z], args.bias[z], nullptr,
                args.C[z], args.oscale[z], smraw);
}

__global__ __launch_bounds__(256, 2) void gemm_h(
    const __half* __restrict__ A, const __half* __restrict__ W,
    const float* __restrict__ bias, float* __restrict__ Cf,
    __half* __restrict__ Ch, float oscale)
{
    extern __shared__ char smraw[];
    gemm_h_body(A, W, bias, Cf, Ch, oscale, smraw);
}

// ============================================================================
// FA2-style fp16 flash attention (R12 proven) + bitmask + x4-trans V loads.
// 64 q x (b*h) per block, 128 threads (4 warps x 16 q-rows, full 64-k stripe).
// ============================================================================
#define ATTNH_SMEM 46080

__global__ __launch_bounds__(128) void attn_h(
    const unsigned long long* __restrict__ mbits)
{
    extern __shared__ char smraw[];
    const uint32_t sQ = smem_u32(smraw);
    const uint32_t sK = sQ + 9216;
    const uint32_t sV = sQ + 27648;

    const int t    = threadIdx.x;
    const int wid  = t >> 5;          // 0..3
    const int lane = t & 31;
    const int grp  = lane >> 2;
    const int tig  = lane & 3;
    const int wm   = wid * 16;
    const int q0   = blockIdx.x * 64;
    const int bh   = blockIdx.y;
    const int b    = bh >> 4;
    const int h    = bh & 15;
    const int hofs = h * HDIM;

    const int lrow = t >> 1;          // loader row 0..63
    const int lcc  = (t & 1) * 4;     // 4 chunks of 16B each

    const int laRow = lane & 15, laCol = (lane >> 4) * 8;
    const int pbRow = ((lane >> 4) & 1) * 8 + (lane & 7);
    const int pbCol = ((lane >> 3) & 1) * 8;
    const int vbRow = lane & 15;
    const int vbCol = ((lane >> 4) & 1) * 8;

    // ---- prologue: Q + K/V tile 0 ----
#pragma unroll
    for (int j = 0; j < 4; j++) {
        int c = lcc + j;
        size_t gq = (size_t)(b * TLEN + q0 + lrow) * EDIM + hofs + c * 8;
        cp_async16(sQ + (lrow * HSTR + c * 8) * 2, g_qh + gq);
        size_t gkv = (size_t)(b * TLEN + lrow) * EDIM + hofs + c * 8;
        cp_async16(sK + (lrow * HSTR + c * 8) * 2, g_kh + gkv);
        cp_async16(sV + (lrow * HSTR + c * 8) * 2, g_vh + gkv);
    }
    CP_COMMIT();

    const int r0 = wm + grp;
    const int r1 = wm + grp + 8;
    const unsigned long long* mrow0 = mbits + (size_t)(b * TLEN + q0 + r0) * 16;
    const unsigned long long* mrow1 = mbits + (size_t)(b * TLEN + q0 + r1) * 16;

    uint32_t qf[4][4];                 // Q fragments, hoisted (constant)
    float o[8][4];
#pragma unroll
    for (int nf = 0; nf < 8; nf++)
#pragma unroll
        for (int q = 0; q < 4; q++) o[nf][q] = 0.0f;
    float mo0 = -1e30f, mo1 = -1e30f, L0 = 0.0f, L1 = 0.0f;

    for (int kt = 0; kt < TLEN / 64; kt++) {
        const int cur = kt & 1;

        // mask bit-words for this tile (2 LDG.64, hoisted)
        const unsigned long long w0 = mrow0[kt];
        const unsigned long long w1 = mrow1[kt];

        CP_WAIT0();
        __syncthreads();

        if (kt == 0) {
#pragma unroll
            for (int ks = 0; ks < 4; ks++)
                ldsm_x4(qf[ks], sQ + ((wm + laRow) * HSTR + ks * 16 + laCol) * 2);
        }

        if (kt + 1 < TLEN / 64) {
            const int nb = cur ^ 1;
            uint32_t kd = sK + nb * 9216;
            uint32_t vd = sV + nb * 9216;
#pragma unroll
            for (int j = 0; j < 4; j++) {
                int c = lcc + j;
                size_t gkv = (size_t)(b * TLEN + (kt + 1) * 64 + lrow) * EDIM + hofs + c * 8;
                cp_async16(kd + (lrow * HSTR + c * 8) * 2, g_kh + gkv);
                cp_async16(vd + (lrow * HSTR + c * 8) * 2, g_vh + gkv);
            }
            CP_COMMIT();
        }

        const uint32_t kB = sK + cur * 9216;
        const uint32_t vB = sV + cur * 9216;

        // ---- S = Q @ K^T over the full 64-k stripe ----
        float s[8][4];
#pragma unroll
        for (int nf = 0; nf < 8; nf++)
#pragma unroll
            for (int q = 0; q < 4; q++) s[nf][q] = 0.0f;

#pragma unroll
        for (int ks = 0; ks < 4; ks++) {
            uint32_t bf[8][2];
#pragma unroll
            for (int njp = 0; njp < 4; njp++) {
                uint32_t r4[4];
                ldsm_x4(r4, kB + ((njp * 16 + pbRow) * HSTR + ks * 16 + pbCol) * 2);
                bf[2 * njp][0] = r4[0]; bf[2 * njp][1] = r4[1];
                bf[2 * njp + 1][0] = r4[2]; bf[2 * njp + 1][1] = r4[3];
            }
#pragma unroll
            for (int nf = 0; nf < 8; nf++)
                mma_f16(s[nf], qf[ks], bf[nf]);
        }

        // ---- mask (bit extract) + in-register row max ----
        float mx0 = -1e30f, mx1 = -1e30f;
#pragma unroll
        for (int nf = 0; nf < 8; nf++) {
            const int sh = nf * 8 + tig * 2;
            s[nf][0] = ((w0 >> sh) & 1ULL) ? s[nf][0] : -1.0e9f;
            s[nf][1] = ((w0 >> sh) & 2ULL) ? s[nf][1] : -1.0e9f;
            s[nf][2] = ((w1 >> sh) & 1ULL) ? s[nf][2] : -1.0e9f;
            s[nf][3] = ((w1 >> sh) & 2ULL) ? s[nf][3] : -1.0e9f;
            mx0 = fmaxf(mx0, fmaxf(s[nf][0], s[nf][1]));
            mx1 = fmaxf(mx1, fmaxf(s[nf][2], s[nf][3]));
        }
        mx0 = fmaxf(mx0, __shfl_xor_sync(0xffffffffu, mx0, 1));
        mx0 = fmaxf(mx0, __shfl_xor_sync(0xffffffffu, mx0, 2));
        mx1 = fmaxf(mx1, __shfl_xor_sync(0xffffffffu, mx1, 1));
        mx1 = fmaxf(mx1, __shfl_xor_sync(0xffffffffu, mx1, 2));

        float mN0 = fmaxf(mo0, mx0);
        float mN1 = fmaxf(mo1, mx1);
        float a0  = __expf(mo0 - mN0);
        float a1  = __expf(mo1 - mN1);
        mo0 = mN0; mo1 = mN1;

        // ---- P = exp(S - m), packed straight into PV A-fragments ----
        uint32_t pp0[8], pp1[8];
        float sum0 = 0.0f, sum1 = 0.0f;
#pragma unroll
        for (int nf = 0; nf < 8; nf++) {
            float p00 = __expf(s[nf][0] - mN0);
            float p01 = __expf(s[nf][1] - mN0);
            float p10 = __expf(s[nf][2] - mN1);
            float p11 = __expf(s[nf][3] - mN1);
            sum0 += p00 + p01;
            sum1 += p10 + p11;
            pp0[nf] = h2pack(p00, p01);
            pp1[nf] = h2pack(p10, p11);
        }
        sum0 += __shfl_xor_sync(0xffffffffu, sum0, 1);
        sum0 += __shfl_xor_sync(0xffffffffu, sum0, 2);
        sum1 += __shfl_xor_sync(0xffffffffu, sum1, 1);
        sum1 += __shfl_xor_sync(0xffffffffu, sum1, 2);
        L0 = L0 * a0 + sum0;
        L1 = L1 * a1 + sum1;

        // ---- rescale O ----
#pragma unroll
        for (int nf = 0; nf < 8; nf++) {
            o[nf][0] *= a0; o[nf][1] *= a0;
            o[nf][2] *= a1; o[nf][3] *= a1;
        }

        // ---- O += P @ V (P in regs; V via ldmatrix.x4.trans, nf-pairs) ----
#pragma unroll
        for (int ks = 0; ks < 4; ks++) {
            uint32_t af[4];
            af[0] = pp0[2 * ks];
            af[1] = pp1[2 * ks];
            af[2] = pp0[2 * ks + 1];
            af[3] = pp1[2 * ks + 1];
#pragma unroll
            for (int nfp = 0; nfp < 4; nfp++) {
                uint32_t r4[4];
                ldsm_x4_t(r4, vB + ((ks * 16 + vbRow) * HSTR + nfp * 16 + vbCol) * 2);
                uint32_t bfa[2] = {r4[0], r4[1]};
                uint32_t bfb[2] = {r4[2], r4[3]};
                mma_f16(o[2 * nfp],     af, bfa);
                mma_f16(o[2 * nfp + 1], af, bfb);
            }
        }
    }

    // ---- normalize + write ----
    const float linv0 = 1.0f / L0;
    const float linv1 = 1.0f / L1;
    const size_t orow0 = (size_t)(b * TLEN + q0 + r0) * EDIM + hofs;
    const size_t orow1 = (size_t)(b * TLEN + q0 + r1) * EDIM + hofs;
#pragma unroll
    for (int nf = 0; nf < 8; nf++) {
        int col = nf * 8 + tig * 2;
        *(__half2*)&g_atth[orow0 + col] =
            __floats2half2_rn(o[nf][0] * linv0, o[nf][1] * linv0);
        *(__half2*)&g_atth[orow1 + col] =
            __floats2half2_rn(o[nf][2] * linv1, o[nf][3] * linv1);
    }
}

// ============================================================================
// LayerNorm over E=1024, one block (256 threads) per row.
// ============================================================================
__global__ __launch_bounds__(256) void ln_kernel(
    const float* __restrict__ X, const float* __restrict__ gam,
    const float* __restrict__ bet, float* __restrict__ out)
{
    const int row = blockIdx.x;
    const int t   = threadIdx.x;
    __shared__ float red[8];

    float4 x = *(const float4*)&X[row * EDIM + t * 4];
    float s = x.x + x.y + x.z + x.w;
#pragma unroll
    for (int ofs = 16; ofs; ofs >>= 1) s += __shfl_xor_sync(0xffffffffu, s, ofs);
    if ((t & 31) == 0) red[t >> 5] = s;
    __syncthreads();
    float tot = 0.0f;
#pragma unroll
    for (int i = 0; i < 8; i++) tot += red[i];
    float mu = tot * (1.0f / 1024.0f);

    float d0 = x.x - mu, d1 = x.y - mu, d2 = x.z - mu, d3 = x.w - mu;
    float sq = d0 * d0 + d1 * d1 + d2 * d2 + d3 * d3;
    __syncthreads();
#pragma unroll
    for (int ofs = 16; ofs; ofs >>= 1) sq += __shfl_xor_sync(0xffffffffu, sq, ofs);
    if ((t & 31) == 0) red[t >> 5] = sq;
    __syncthreads();
    float vtot = 0.0f;
#pragma unroll
    for (int i = 0; i < 8; i++) vtot += red[i];
    float inv = rsqrtf(vtot * (1.0f / 1024.0f) + 1e-5f);

    float4 g  = *(const float4*)&gam[t * 4];
    float4 be = *(const float4*)&bet[t * 4];
    float4 o4;
    o4.x = d0 * inv * g.x + be.x;
    o4.y = d1 * inv * g.y + be.y;
    o4.z = d2 * inv * g.z + be.z;
    o4.w = d3 * inv * g.w + be.w;
    *(float4*)&out[row * EDIM + t * 4] = o4;
}

// ============================================================================
extern "C" void kernel_launch(void* const* d_in, const int* in_sizes, int n_in,
                              void* d_out, int out_size)
{
    const float* query = (const float*)d_in[0];
    const float* key   = (const float*)d_in[1];
    const float* value = (const float*)d_in[2];
    const int*   mask  = (const int*)d_in[3];
    const float* Wq    = (const float*)d_in[4];
    const float* bq    = (const float*)d_in[5];
    const float* Wk    = (const float*)d_in[6];
    const float* bk    = (const float*)d_in[7];
    const float* Wv    = (const float*)d_in[8];
    const float* bv    = (const float*)d_in[9];
    const float* Wo    = (const float*)d_in[10];
    const float* bo    = (const float*)d_in[11];
    const float* gamma = (const float*)d_in[12];
    const float* beta  = (const float*)d_in[13];
    float* out = (float*)d_out;

    __half *hx, *hw, *qh, *kh, *vh, *atth;
    float* go;
    unsigned long long* mb;
    cudaGetSymbolAddress((void**)&hx,   g_hx);
    cudaGetSymbolAddress((void**)&hw,   g_hw);
    cudaGetSymbolAddress((void**)&qh,   g_qh);
    cudaGetSymbolAddress((void**)&kh,   g_kh);
    cudaGetSymbolAddress((void**)&vh,   g_vh);
    cudaGetSymbolAddress((void**)&atth, g_atth);
    cudaGetSymbolAddress((void**)&go,   g_o);
    cudaGetSymbolAddress((void**)&mb,   g_mbits);

    const size_t ACT = (size_t)MROWS * EDIM;
    const size_t WSZ = (size_t)EDIM * EDIM;

    cudaFuncSetAttribute(gemm_h,
                         cudaFuncAttributeMaxDynamicSharedMemorySize, GEMMH_SMEM);
    cudaFuncSetAttribute(gemm_h3,
                         cudaFuncAttributeMaxDynamicSharedMemorySize, GEMMH_SMEM);
    cudaFuncSetAttribute(attn_h,
                         cudaFuncAttributeMaxDynamicSharedMemorySize, ATTNH_SMEM);

    // fp32 -> fp16 conversion (MLP=4) + mask bit-packing
    CvtArgs ca;
    ca.x[0] = query; ca.x[1] = key; ca.x[2] = value;
    ca.x[3] = Wq; ca.x[4] = Wk; ca.x[5] = Wv; ca.x[6] = Wo;
    ca.y[0] = hx;           ca.y[1] = hx + ACT;   ca.y[2] = hx + 2 * ACT;
    ca.y[3] = hw;           ca.y[4] = hw + WSZ;
    ca.y[5] = hw + 2 * WSZ; ca.y[6] = hw + 3 * WSZ;
    dim3 gc(CVT_GRID_X, 7);
    cvt7_kernel<<<gc, 256>>>(ca);
    maskpack_kernel<<<256, 256>>>(mask, mb);

    // batched QKV projections
    G3Args g3;
    g3.A[0] = hx;           g3.A[1] = hx + ACT;   g3.A[2] = hx + 2 * ACT;
    g3.W[0] = hw;           g3.W[1] = hw + WSZ;   g3.W[2] = hw + 2 * WSZ;
    g3.bias[0] = bq; g3.bias[1] = bk; g3.bias[2] = bv;
    g3.C[0] = qh; g3.C[1] = kh; g3.C[2] = vh;
    g3.oscale[0] = 0.125f; g3.oscale[1] = 1.0f; g3.oscale[2] = 1.0f;
    dim3 gg3(EDIM / 128, MROWS / 128, 3);   // (8, 32, 3)
    gemm_h3<<<gg3, 256, GEMMH_SMEM>>>(g3);

    dim3 ga(TLEN / 64, BATCH * NHEAD);      // (16, 64)
    attn_h<<<ga, 128, ATTNH_SMEM>>>(mb);

    dim3 gg(EDIM / 128, MROWS / 128);       // (8, 32)
    gemm_h<<<gg, 256, GEMMH_SMEM>>>(atth, hw + 3 * WSZ, bo, go, nullptr, 1.0f);

    ln_kernel<<<MROWS, 256>>>(go, gamma, beta, out);
}